// round 13
// baseline (speedup 1.0000x reference)
#include <cuda_runtime.h>
#include <cuda_bf16.h>

#define N_NODES 50000
#define N_EDGES 640000
#define NELEM (N_NODES * 128)
#define NBLK 196

// ---------------- scratch (device globals) ----------------
__device__ __align__(16) __nv_bfloat16 g_xhi[NELEM], g_xlo[NELEM];
__device__ __align__(16) __nv_bfloat16 g_hhi[3][NELEM], g_hlo[3][NELEM];
__device__ __align__(16) __nv_bfloat16 g_wthi[6][128 * 128], g_wtlo[6][128 * 128];
__device__ __align__(16) __nv_bfloat16 g_fwthi[128 * 512], g_fwtlo[128 * 512];
__device__ int g_rowptr[N_NODES + 1], g_cnt[N_NODES], g_cnt2[N_NODES], g_srcs[N_EDGES];
__device__ int g_is64, g_bsum[256];

// ---------------- fused prep: zero cnt + detect dtype + split x + split W ----
__global__ void prep_kernel(const float* __restrict__ x, const int* __restrict__ ei32,
                            const float* __restrict__ W1, const float* __restrict__ W2,
                            const float* __restrict__ fw) {
    int i = blockIdx.x * 256 + threadIdx.x;
    if (i < N_NODES) g_cnt[i] = 0;
    if (i == 0) {
        int ornz = 0;
#pragma unroll
        for (int k = 0; k < 64; k++) ornz |= ei32[2 * k + 1];
        g_is64 = (ornz == 0) ? 1 : 0;
    }
    if (i < 6 * 16384) {
        int m = i >> 14, t = i & 16383;
        int n = t >> 7, k = t & 127;
        int l = m >> 1;
        const float* src = (m & 1) ? W2 : W1;
        float v = src[l * 16384 + k * 128 + n];
        __nv_bfloat16 h = __float2bfloat16_rn(v);
        g_wthi[m][n * 128 + k] = h;
        g_wtlo[m][n * 128 + k] = __float2bfloat16_rn(v - __bfloat162float(h));
    } else if (i < 6 * 16384 + 128 * 512) {
        int t = i - 6 * 16384;
        int n = t >> 9, k = t & 511;
        float v = fw[k * 128 + n];
        __nv_bfloat16 h = __float2bfloat16_rn(v);
        g_fwthi[n * 512 + k] = h;
        g_fwtlo[n * 512 + k] = __float2bfloat16_rn(v - __bfloat162float(h));
    }
    if (i < NELEM / 8) {
        const float4* xp = (const float4*)x;
        float4 v0 = xp[2 * i], v1 = xp[2 * i + 1];
        float v[8] = {v0.x, v0.y, v0.z, v0.w, v1.x, v1.y, v1.z, v1.w};
        uint4 hp, lp;
        __nv_bfloat162* h2 = (__nv_bfloat162*)&hp;
        __nv_bfloat162* l2 = (__nv_bfloat162*)&lp;
#pragma unroll
        for (int j = 0; j < 4; j++) {
            __nv_bfloat16 h0 = __float2bfloat16_rn(v[2 * j]);
            __nv_bfloat16 h1 = __float2bfloat16_rn(v[2 * j + 1]);
            h2[j].x = h0; h2[j].y = h1;
            l2[j].x = __float2bfloat16_rn(v[2 * j] - __bfloat162float(h0));
            l2[j].y = __float2bfloat16_rn(v[2 * j + 1] - __bfloat162float(h1));
        }
        ((uint4*)g_xhi)[i] = hp;
        ((uint4*)g_xlo)[i] = lp;
    }
}

// ---------------- CSR build (8 edges/thread) ----------------
__global__ void hist_kernel(const int* __restrict__ ei32) {
    int e = (blockIdx.x * 256 + threadIdx.x) * 8;
    if (e >= N_EDGES) return;
    int is64 = g_is64;
    int d[8];
    if (is64) {
#pragma unroll
        for (int q = 0; q < 4; q++) {
            int4 a = *(const int4*)&ei32[2 * (N_EDGES + e) + 4 * q];
            d[2 * q] = a.x; d[2 * q + 1] = a.z;
        }
    } else {
        int4 a = *(const int4*)&ei32[N_EDGES + e];
        int4 b = *(const int4*)&ei32[N_EDGES + e + 4];
        d[0] = a.x; d[1] = a.y; d[2] = a.z; d[3] = a.w;
        d[4] = b.x; d[5] = b.y; d[6] = b.z; d[7] = b.w;
    }
#pragma unroll
    for (int q = 0; q < 8; q++)
        if ((unsigned)d[q] < (unsigned)N_NODES) atomicAdd(&g_cnt[d[q]], 1);
}

__global__ void bsum_kernel() {
    __shared__ int sh[256];
    int t = threadIdx.x, i = blockIdx.x * 256 + t;
    if (i < N_NODES) g_cnt2[i] = 0;
    sh[t] = (i < N_NODES) ? g_cnt[i] : 0;
    __syncthreads();
#pragma unroll
    for (int off = 128; off > 0; off >>= 1) {
        if (t < off) sh[t] += sh[t + off];
        __syncthreads();
    }
    if (t == 0) g_bsum[blockIdx.x] = sh[0];
}

__global__ void rowptr_kernel() {
    __shared__ int sb[256];
    __shared__ int sh[256];
    int t = threadIdx.x, i = blockIdx.x * 256 + t;
    int bv = (t < NBLK) ? g_bsum[t] : 0;
    sb[t] = bv;
    __syncthreads();
#pragma unroll
    for (int off = 1; off < 256; off <<= 1) {
        int a = (t >= off) ? sb[t - off] : 0;
        __syncthreads();
        sb[t] += a;
        __syncthreads();
    }
    int boff = sb[blockIdx.x] - g_bsum[blockIdx.x];
    if (blockIdx.x == 0 && t == 0) g_rowptr[N_NODES] = sb[255];

    int v = (i < N_NODES) ? g_cnt[i] : 0;
    sh[t] = v;
    __syncthreads();
#pragma unroll
    for (int off = 1; off < 256; off <<= 1) {
        int a = (t >= off) ? sh[t - off] : 0;
        __syncthreads();
        sh[t] += a;
        __syncthreads();
    }
    if (i < N_NODES) g_rowptr[i] = boff + sh[t] - v;
}

__global__ void scatter_kernel(const int* __restrict__ ei32) {
    int e = (blockIdx.x * 256 + threadIdx.x) * 8;
    if (e >= N_EDGES) return;
    int is64 = g_is64;
    int s[8], d[8];
    if (is64) {
#pragma unroll
        for (int q = 0; q < 4; q++) {
            int4 a = *(const int4*)&ei32[2 * e + 4 * q];
            s[2 * q] = a.x; s[2 * q + 1] = a.z;
            int4 c = *(const int4*)&ei32[2 * (N_EDGES + e) + 4 * q];
            d[2 * q] = c.x; d[2 * q + 1] = c.z;
        }
    } else {
        int4 a = *(const int4*)&ei32[e];
        int4 b = *(const int4*)&ei32[e + 4];
        s[0] = a.x; s[1] = a.y; s[2] = a.z; s[3] = a.w;
        s[4] = b.x; s[5] = b.y; s[6] = b.z; s[7] = b.w;
        int4 c = *(const int4*)&ei32[N_EDGES + e];
        int4 f = *(const int4*)&ei32[N_EDGES + e + 4];
        d[0] = c.x; d[1] = c.y; d[2] = c.z; d[3] = c.w;
        d[4] = f.x; d[5] = f.y; d[6] = f.z; d[7] = f.w;
    }
#pragma unroll
    for (int q = 0; q < 8; q++) {
        if ((unsigned)d[q] < (unsigned)N_NODES && (unsigned)s[q] < (unsigned)N_NODES) {
            int pos = g_rowptr[d[q]] + atomicAdd(&g_cnt2[d[q]], 1);
            if ((unsigned)pos < (unsigned)N_EDGES) g_srcs[pos] = s[q];
        }
    }
}

// ---------------- async-copy / mma helpers ----------------
__device__ __forceinline__ void cp16(unsigned s, const void* g, bool pred) {
    int sz = pred ? 16 : 0;
    asm volatile("cp.async.cg.shared.global [%0], [%1], 16, %2;\n"
                 :: "r"(s), "l"(g), "r"(sz));
}
__device__ __forceinline__ void cp_commit() { asm volatile("cp.async.commit_group;\n"); }
template <int N>
__device__ __forceinline__ void cp_wait() {
    asm volatile("cp.async.wait_group %0;\n" :: "n"(N) : "memory");
}
__device__ __forceinline__ void ldsm4(unsigned* r, unsigned addr) {
    asm volatile("ldmatrix.sync.aligned.m8n8.x4.shared.b16 {%0,%1,%2,%3}, [%4];"
                 : "=r"(r[0]), "=r"(r[1]), "=r"(r[2]), "=r"(r[3]) : "r"(addr));
}
__device__ __forceinline__ void mma_bf16(float* c, const unsigned* a, const unsigned* b) {
    asm volatile(
        "mma.sync.aligned.m16n8k16.row.col.f32.bf16.bf16.f32 "
        "{%0,%1,%2,%3},{%4,%5,%6,%7},{%8,%9},{%0,%1,%2,%3};"
        : "+f"(c[0]), "+f"(c[1]), "+f"(c[2]), "+f"(c[3])
        : "r"(a[0]), "r"(a[1]), "r"(a[2]), "r"(a[3]), "r"(b[0]), "r"(b[1]));
}
__device__ __forceinline__ void store_hl(__nv_bfloat16* Ohi, __nv_bfloat16* Olo,
                                         long long off, float v0, float v1) {
    __nv_bfloat16 h0 = __float2bfloat16_rn(v0), h1 = __float2bfloat16_rn(v1);
    __nv_bfloat162 hp; hp.x = h0; hp.y = h1;
    *(__nv_bfloat162*)(Ohi + off) = hp;
    __nv_bfloat162 lp;
    lp.x = __float2bfloat16_rn(v0 - __bfloat162float(h0));
    lp.y = __float2bfloat16_rn(v1 - __bfloat162float(h1));
    *(__nv_bfloat162*)(Olo + off) = lp;
}

// ================= fused layer kernel =================
// smem: W stages [0, 49152): stage s = {Whi @ s*12288, Wlo @ s*12288+6144}
//       resident A: Ahi @ 49152 (32KB), Alo @ 81920 (32KB); rows 256B, XOR swizzle
#define LW_STAGE 12288u
#define LA_HI 49152u
#define LA_LO 81920u
#define LSMEM_BYTES 114688

// stream one K=128 GEMM over resident A with W from global (4-stage pipeline)
__device__ __forceinline__ void gemm_resA(unsigned sbase, unsigned aHi, unsigned aLo,
                                          const __nv_bfloat16* __restrict__ Whi_g,
                                          const __nv_bfloat16* __restrict__ Wlo_g,
                                          int wm, int lane, const int* woff,
                                          unsigned dsto, int crow, int chalf,
                                          float acc[2][8][4], bool do_prologue) {
    if (do_prologue) {
#pragma unroll
        for (int pc = 0; pc < 3; pc++) {
            unsigned st = sbase + (unsigned)pc * LW_STAGE;
            int kb = pc * 16 + chalf * 8;
            cp16(st + dsto, Whi_g + crow * 128 + kb, true);
            cp16(st + 6144 + dsto, Wlo_g + crow * 128 + kb, true);
            cp_commit();
        }
    }
    const int g = lane >> 3, r = lane & 7;
#pragma unroll
    for (int c = 0; c < 8; c++) {
        if (c < 6) cp_wait<2>();
        else if (c == 6) cp_wait<1>();
        else cp_wait<0>();
        __syncthreads();
        unsigned ah[2][4], al[2][4];
        const int colc = 2 * c + (g >> 1);
#pragma unroll
        for (int mi = 0; mi < 2; mi++) {
            int row = wm * 32 + mi * 16 + (g & 1) * 8 + r;
            unsigned off = (unsigned)(row * 256 + ((colc ^ (row & 7)) << 4));
            ldsm4(ah[mi], aHi + off);
            ldsm4(al[mi], aLo + off);
        }
        unsigned wb = sbase + (unsigned)(c & 3) * LW_STAGE;
#pragma unroll
        for (int ng = 0; ng < 4; ng++) {
            unsigned bh[4], bl[4];
            ldsm4(bh, wb + woff[ng]);
            ldsm4(bl, wb + 6144 + woff[ng]);
#pragma unroll
            for (int mi = 0; mi < 2; mi++)
#pragma unroll
                for (int ns = 0; ns < 2; ns++) {
                    float* C = acc[mi][ng * 2 + ns];
                    mma_bf16(C, ah[mi], &bh[ns * 2]);
                    mma_bf16(C, ah[mi], &bl[ns * 2]);
                    mma_bf16(C, al[mi], &bh[ns * 2]);
                }
        }
        if (c + 3 < 8) {
            unsigned st = sbase + (unsigned)((c + 3) & 3) * LW_STAGE;
            int kb = (c + 3) * 16 + chalf * 8;
            cp16(st + dsto, Whi_g + crow * 128 + kb, true);
            cp16(st + 6144 + dsto, Wlo_g + crow * 128 + kb, true);
            cp_commit();
        }
    }
}

__global__ void __launch_bounds__(256, 2)
layer_kernel(int lidx, const float* __restrict__ b1, const float* __restrict__ b2,
             const float* __restrict__ eps) {
    extern __shared__ __align__(16) unsigned char lsm[];
    const unsigned sbase = (unsigned)__cvta_generic_to_shared(lsm);
    const unsigned aHi = sbase + LA_HI, aLo = sbase + LA_LO;

    const __nv_bfloat16 *Phi, *Plo;
    if (lidx == 0) { Phi = g_xhi; Plo = g_xlo; }
    else           { Phi = g_hhi[lidx - 1]; Plo = g_hlo[lidx - 1]; }
    __nv_bfloat16* Ohi = g_hhi[lidx];
    __nv_bfloat16* Olo = g_hlo[lidx];
    const __nv_bfloat16* W1hi = g_wthi[2 * lidx];
    const __nv_bfloat16* W1lo = g_wtlo[2 * lidx];
    const __nv_bfloat16* W2hi = g_wthi[2 * lidx + 1];
    const __nv_bfloat16* W2lo = g_wtlo[2 * lidx + 1];

    const int tid = threadIdx.x, lane = tid & 31, w = tid >> 5;
    const int wm = w & 3, wn = w >> 2;
    const int rowBase = blockIdx.x * 128;
    const int crow = tid >> 1, chalf = tid & 1;
    const unsigned dsto = (unsigned)(crow * 48 + chalf * 16);

    int woff[4];
    {
        const int g = lane >> 3, r = lane & 7;
#pragma unroll
        for (int ng = 0; ng < 4; ng++)
            woff[ng] = (wn * 64 + ng * 16 + (g >> 1) * 8 + r) * 48 + (g & 1) * 16;
    }

    // issue W1 prologue BEFORE agg so the loads hide under the gather
#pragma unroll
    for (int pc = 0; pc < 3; pc++) {
        unsigned st = sbase + (unsigned)pc * LW_STAGE;
        int kb = pc * 16 + chalf * 8;
        cp16(st + dsto, W1hi + crow * 128 + kb, true);
        cp16(st + 6144 + dsto, W1lo + crow * 128 + kb, true);
        cp_commit();
    }

    // ---- Phase 1: aggregation t = (1+eps)*h + segsum -> smem (swizzled) ----
    {
        const int half = lane >> 4, p = lane & 15;
        const uint4* rows = (const uint4*)(half ? Plo : Phi);
        const float e = 1.0f + eps[lidx];
        uint4* dstmat = (uint4*)(lsm + (half ? LA_LO : LA_HI));
        for (int j = 0; j < 16; j++) {
            const int lr = w * 16 + j;
            const int node = rowBase + lr;
            uint4 outv = make_uint4(0, 0, 0, 0);
            if (node < N_NODES) {
                float acc[8];
#pragma unroll
                for (int q = 0; q < 8; q++) acc[q] = 0.f;
                int beg = g_rowptr[node], end = g_rowptr[node + 1];
                int i = beg;
                for (; i + 4 <= end; i += 4) {
                    int s0 = g_srcs[i], s1 = g_srcs[i + 1];
                    int s2 = g_srcs[i + 2], s3 = g_srcs[i + 3];
                    uint4 v0 = rows[s0 * 16 + p];
                    uint4 v1 = rows[s1 * 16 + p];
                    uint4 v2 = rows[s2 * 16 + p];
                    uint4 v3 = rows[s3 * 16 + p];
                    const __nv_bfloat162* p0 = (const __nv_bfloat162*)&v0;
                    const __nv_bfloat162* p1 = (const __nv_bfloat162*)&v1;
                    const __nv_bfloat162* p2 = (const __nv_bfloat162*)&v2;
                    const __nv_bfloat162* p3 = (const __nv_bfloat162*)&v3;
#pragma unroll
                    for (int q = 0; q < 4; q++) {
                        float2 f0 = __bfloat1622float2(p0[q]);
                        float2 f1 = __bfloat1622float2(p1[q]);
                        float2 f2 = __bfloat1622float2(p2[q]);
                        float2 f3 = __bfloat1622float2(p3[q]);
                        acc[2 * q]     += (f0.x + f1.x) + (f2.x + f3.x);
                        acc[2 * q + 1] += (f0.y + f1.y) + (f2.y + f3.y);
                    }
                }
                for (; i < end; i++) {
                    uint4 v = rows[g_srcs[i] * 16 + p];
                    const __nv_bfloat162* pv = (const __nv_bfloat162*)&v;
#pragma unroll
                    for (int q = 0; q < 4; q++) {
                        float2 f = __bfloat1622float2(pv[q]);
                        acc[2 * q] += f.x;
                        acc[2 * q + 1] += f.y;
                    }
                }
                {   // self term
                    uint4 v = rows[node * 16 + p];
                    const __nv_bfloat162* pv = (const __nv_bfloat162*)&v;
#pragma unroll
                    for (int q = 0; q < 4; q++) {
                        float2 f = __bfloat1622float2(pv[q]);
                        acc[2 * q] += e * f.x;
                        acc[2 * q + 1] += e * f.y;
                    }
                }
                float tot[8];
#pragma unroll
                for (int q = 0; q < 8; q++)
                    tot[q] = acc[q] + __shfl_xor_sync(0xffffffffu, acc[q], 16);
                __nv_bfloat162* o2 = (__nv_bfloat162*)&outv;
#pragma unroll
                for (int q = 0; q < 4; q++) {
                    __nv_bfloat16 h0 = __float2bfloat16_rn(tot[2 * q]);
                    __nv_bfloat16 h1 = __float2bfloat16_rn(tot[2 * q + 1]);
                    if (half == 0) { o2[q].x = h0; o2[q].y = h1; }
                    else {
                        o2[q].x = __float2bfloat16_rn(tot[2 * q] - __bfloat162float(h0));
                        o2[q].y = __float2bfloat16_rn(tot[2 * q + 1] - __bfloat162float(h1));
                    }
                }
            }
            dstmat[lr * 16 + (p ^ (lr & 7))] = outv;
        }
    }
    __syncthreads();

    // ---- Phase 2: GEMM1 (A = t resident), z -> smem ----
    float acc[2][8][4];
#pragma unroll
    for (int i = 0; i < 2; i++)
#pragma unroll
        for (int j = 0; j < 8; j++)
#pragma unroll
            for (int q = 0; q < 4; q++) acc[i][j][q] = 0.f;

    gemm_resA(sbase, aHi, aLo, W1hi, W1lo, wm, lane, woff, dsto, crow, chalf,
              acc, false /* prologue already issued */);
    __syncthreads();   // all warps finished reading t before z overwrite

    // z epilogue: bias + relu, split-store into resident A region
#pragma unroll
    for (int ni = 0; ni < 8; ni++) {
        int n0 = wn * 64 + ni * 8 + 2 * (lane & 3);
        float2 bv = *(const float2*)&b1[n0];
        int chunkBase = n0 >> 3;            // wn*8 + ni
        int within = (n0 * 2) & 15;         // 4*(lane&3)
#pragma unroll
        for (int mi = 0; mi < 2; mi++) {
            float* C = acc[mi][ni];
            int r0 = wm * 32 + mi * 16 + (lane >> 2);
#pragma unroll
            for (int rr = 0; rr < 2; rr++) {
                int row = r0 + rr * 8;
                float v0 = fmaxf(C[2 * rr] + bv.x, 0.f);
                float v1 = fmaxf(C[2 * rr + 1] + bv.y, 0.f);
                __nv_bfloat16 h0 = __float2bfloat16_rn(v0), h1 = __float2bfloat16_rn(v1);
                __nv_bfloat162 hp; hp.x = h0; hp.y = h1;
                __nv_bfloat162 lp;
                lp.x = __float2bfloat16_rn(v0 - __bfloat162float(h0));
                lp.y = __float2bfloat16_rn(v1 - __bfloat162float(h1));
                unsigned byteoff = (unsigned)(row * 256 + ((chunkBase ^ (row & 7)) << 4) + within);
                *(__nv_bfloat162*)(lsm + LA_HI + byteoff) = hp;
                *(__nv_bfloat162*)(lsm + LA_LO + byteoff) = lp;
            }
        }
    }
    __syncthreads();

    // ---- Phase 3: GEMM2 (A = z resident), h -> global ----
#pragma unroll
    for (int i = 0; i < 2; i++)
#pragma unroll
        for (int j = 0; j < 8; j++)
#pragma unroll
            for (int q = 0; q < 4; q++) acc[i][j][q] = 0.f;

    gemm_resA(sbase, aHi, aLo, W2hi, W2lo, wm, lane, woff, dsto, crow, chalf,
              acc, true);

#pragma unroll
    for (int ni = 0; ni < 8; ni++) {
        int n0 = wn * 64 + ni * 8 + 2 * (lane & 3);
        float2 bv = *(const float2*)&b2[n0];
#pragma unroll
        for (int mi = 0; mi < 2; mi++) {
            int r0 = rowBase + wm * 32 + mi * 16 + (lane >> 2);
            float* C = acc[mi][ni];
            float v0 = fmaxf(C[0] + bv.x, 0.f), v1 = fmaxf(C[1] + bv.y, 0.f);
            float v2 = fmaxf(C[2] + bv.x, 0.f), v3 = fmaxf(C[3] + bv.y, 0.f);
            if (r0 < N_NODES) store_hl(Ohi, Olo, (long long)r0 * 128 + n0, v0, v1);
            if (r0 + 8 < N_NODES) store_hl(Ohi, Olo, (long long)(r0 + 8) * 128 + n0, v2, v3);
        }
    }
}

// ---------------- final GEMM: out = concat(x,h0,h1,h2) @ fw + fb, K=512 ------
#define MAT_BYTES 6144u
#define SMEM_BYTES (4 * 4 * MAT_BYTES)   // 98304

__device__ __forceinline__ void mma_chunk(unsigned mbase, int aoff0, int aoff1,
                                          const int* woff, float acc[2][8][4]) {
    unsigned ah[2][4], al[2][4];
    ldsm4(ah[0], mbase + 0 * MAT_BYTES + aoff0);
    ldsm4(ah[1], mbase + 0 * MAT_BYTES + aoff1);
    ldsm4(al[0], mbase + 1 * MAT_BYTES + aoff0);
    ldsm4(al[1], mbase + 1 * MAT_BYTES + aoff1);
#pragma unroll
    for (int ng = 0; ng < 4; ng++) {
        unsigned bh[4], bl[4];
        ldsm4(bh, mbase + 2 * MAT_BYTES + woff[ng]);
        ldsm4(bl, mbase + 3 * MAT_BYTES + woff[ng]);
#pragma unroll
        for (int mi = 0; mi < 2; mi++)
#pragma unroll
            for (int ns = 0; ns < 2; ns++) {
                float* C = acc[mi][ng * 2 + ns];
                mma_bf16(C, ah[mi], &bh[ns * 2]);
                mma_bf16(C, ah[mi], &bl[ns * 2]);
                mma_bf16(C, al[mi], &bh[ns * 2]);
            }
    }
}

__device__ __forceinline__ void final_src(int s, const __nv_bfloat16*& hi,
                                          const __nv_bfloat16*& lo) {
    switch (s) {
        case 0: hi = g_xhi; lo = g_xlo; break;
        case 1: hi = g_hhi[0]; lo = g_hlo[0]; break;
        case 2: hi = g_hhi[1]; lo = g_hlo[1]; break;
        default: hi = g_hhi[2]; lo = g_hlo[2]; break;
    }
}

__global__ void __launch_bounds__(256, 2)
final_gemm_kernel(const float* __restrict__ fb, float* __restrict__ out) {
    extern __shared__ __nv_bfloat16 dynsm[];
    const unsigned base = (unsigned)__cvta_generic_to_shared(dynsm);

    const int tid = threadIdx.x, lane = tid & 31, w = tid >> 5;
    const int wm = w & 3, wn = w >> 2;
    const int rowBase = blockIdx.x * 128;
    const int g = lane >> 3, r = lane & 7;

    const int aoff0 = (wm * 32 + 0 + (g & 1) * 8 + r) * 48 + (g >> 1) * 16;
    const int aoff1 = (wm * 32 + 16 + (g & 1) * 8 + r) * 48 + (g >> 1) * 16;
    int woff[4];
#pragma unroll
    for (int ng = 0; ng < 4; ng++)
        woff[ng] = (wn * 64 + ng * 16 + (g >> 1) * 8 + r) * 48 + (g & 1) * 16;

    float acc[2][8][4];
#pragma unroll
    for (int i = 0; i < 2; i++)
#pragma unroll
        for (int j = 0; j < 8; j++)
#pragma unroll
            for (int q = 0; q < 4; q++) acc[i][j][q] = 0.f;

    const int crow = tid >> 1, chalf = tid & 1;
    const unsigned dsto = (unsigned)(crow * 48 + chalf * 16);
    const bool aok = (rowBase + crow) < N_NODES;
    const long long arow = (long long)(rowBase + crow) * 128;

#pragma unroll
    for (int pc = 0; pc < 3; pc++) {
        const __nv_bfloat16 *shi, *slo;
        final_src(pc >> 3, shi, slo);
        unsigned mb = base + (unsigned)pc * 4 * MAT_BYTES;
        int ka = (pc & 7) * 16 + chalf * 8;
        int kw = pc * 16 + chalf * 8;
        cp16(mb + 0 * MAT_BYTES + dsto, shi + arow + ka, aok);
        cp16(mb + 1 * MAT_BYTES + dsto, slo + arow + ka, aok);
        cp16(mb + 2 * MAT_BYTES + dsto, g_fwthi + crow * 512 + kw, true);
        cp16(mb + 3 * MAT_BYTES + dsto, g_fwtlo + crow * 512 + kw, true);
        cp_commit();
    }

    for (int c = 0; c < 32; c++) {
        if (c < 30) cp_wait<2>();
        else if (c == 30) cp_wait<1>();
        else cp_wait<0>();
        __syncthreads();
        mma_chunk(base + (unsigned)(c & 3) * 4 * MAT_BYTES, aoff0, aoff1, woff, acc);
        if (c + 3 < 32) {
            int cn = c + 3;
            const __nv_bfloat16 *shi, *slo;
            final_src(cn >> 3, shi, slo);
            unsigned mb = base + (unsigned)(cn & 3) * 4 * MAT_BYTES;
            int ka = (cn & 7) * 16 + chalf * 8;
            int kw = cn * 16 + chalf * 8;
            cp16(mb + 0 * MAT_BYTES + dsto, shi + arow + ka, aok);
            cp16(mb + 1 * MAT_BYTES + dsto, slo + arow + ka, aok);
            cp16(mb + 2 * MAT_BYTES + dsto, g_fwthi + crow * 512 + kw, true);
            cp16(mb + 3 * MAT_BYTES + dsto, g_fwtlo + crow * 512 + kw, true);
            cp_commit();
        }
    }

#pragma unroll
    for (int ni = 0; ni < 8; ni++) {
        int n0 = wn * 64 + ni * 8 + 2 * (lane & 3);
        float2 bv = *(const float2*)&fb[n0];
#pragma unroll
        for (int mi = 0; mi < 2; mi++) {
            int r0 = rowBase + wm * 32 + mi * 16 + (lane >> 2);
            float* C = acc[mi][ni];
            if (r0 < N_NODES) {
                float2 o = make_float2(C[0] + bv.x, C[1] + bv.y);
                *(float2*)&out[(long long)r0 * 128 + n0] = o;
            }
            if (r0 + 8 < N_NODES) {
                float2 o = make_float2(C[2] + bv.x, C[3] + bv.y);
                *(float2*)&out[(long long)(r0 + 8) * 128 + n0] = o;
            }
        }
    }
}

// ---------------- launch ----------------
extern "C" void kernel_launch(void* const* d_in, const int* in_sizes, int n_in,
                              void* d_out, int out_size) {
    const float* x   = (const float*)d_in[0];
    const int*   ei  = (const int*)d_in[1];
    const float* W1  = (const float*)d_in[2];
    const float* b1  = (const float*)d_in[3];
    const float* W2  = (const float*)d_in[4];
    const float* b2  = (const float*)d_in[5];
    const float* eps = (const float*)d_in[6];
    const float* fw  = (const float*)d_in[7];
    const float* fb  = (const float*)d_in[8];
    float* out = (float*)d_out;

    cudaFuncSetAttribute(layer_kernel,
                         cudaFuncAttributeMaxDynamicSharedMemorySize, LSMEM_BYTES);
    cudaFuncSetAttribute(final_gemm_kernel,
                         cudaFuncAttributeMaxDynamicSharedMemorySize, SMEM_BYTES);

    const int PB = (NELEM / 8 + 255) / 256;          // 3125
    const int EB8 = (N_EDGES / 8 + 255) / 256;       // 313
    const int GB = (N_NODES + 127) / 128;            // 391

    // fused prep + CSR build
    prep_kernel<<<PB, 256>>>(x, ei, W1, W2, fw);
    hist_kernel<<<EB8, 256>>>(ei);
    bsum_kernel<<<NBLK, 256>>>();
    rowptr_kernel<<<NBLK, 256>>>();
    scatter_kernel<<<EB8, 256>>>(ei);

    // 3 fused GIN layers (agg + MLP in one kernel each)
    for (int l = 0; l < 3; l++)
        layer_kernel<<<GB, 256, LSMEM_BYTES>>>(l, b1 + l * 128, b2 + l * 128, eps);

    final_gemm_kernel<<<GB, 256, SMEM_BYTES>>>(fb, out);
}

// round 14
// speedup vs baseline: 1.1833x; 1.1833x over previous
#include <cuda_runtime.h>
#include <cuda_bf16.h>

#define N_NODES 50000
#define N_EDGES 640000
#define NELEM (N_NODES * 128)
#define NBLK 196

// ---------------- scratch (device globals) ----------------
__device__ __align__(16) __nv_bfloat16 g_xhi[NELEM], g_xlo[NELEM];
__device__ __align__(16) __nv_bfloat16 g_thi[NELEM], g_tlo[NELEM];
__device__ __align__(16) __nv_bfloat16 g_zhi[NELEM], g_zlo[NELEM];
__device__ __align__(16) __nv_bfloat16 g_hhi[3][NELEM], g_hlo[3][NELEM];
__device__ __align__(16) __nv_bfloat16 g_wthi[6][128 * 128], g_wtlo[6][128 * 128];
__device__ __align__(16) __nv_bfloat16 g_fwthi[128 * 512], g_fwtlo[128 * 512];
__device__ int g_rowptr[N_NODES + 1], g_cnt[N_NODES], g_cnt2[N_NODES], g_srcs[N_EDGES];
__device__ int g_is64, g_bsum[256];

#define SEL_X 0
#define SEL_T 1
#define SEL_Z 2
#define SEL_H0 3
#define SEL_H1 4
#define SEL_H2 5

__device__ __forceinline__ void sel_hl(int s, const __nv_bfloat16*& hi,
                                       const __nv_bfloat16*& lo) {
    switch (s) {
        case SEL_X: hi = g_xhi; lo = g_xlo; break;
        case SEL_T: hi = g_thi; lo = g_tlo; break;
        case SEL_Z: hi = g_zhi; lo = g_zlo; break;
        case SEL_H0: hi = g_hhi[0]; lo = g_hlo[0]; break;
        case SEL_H1: hi = g_hhi[1]; lo = g_hlo[1]; break;
        default:     hi = g_hhi[2]; lo = g_hlo[2]; break;
    }
}
__device__ __forceinline__ void sel_out(int s, __nv_bfloat16*& hi, __nv_bfloat16*& lo) {
    switch (s) {
        case SEL_T: hi = g_thi; lo = g_tlo; break;
        case SEL_Z: hi = g_zhi; lo = g_zlo; break;
        case SEL_H0: hi = g_hhi[0]; lo = g_hlo[0]; break;
        case SEL_H1: hi = g_hhi[1]; lo = g_hlo[1]; break;
        default:     hi = g_hhi[2]; lo = g_hlo[2]; break;
    }
}

// ---------------- fused prep: zero cnt + detect dtype + split x + split W ----
__global__ void prep_kernel(const float* __restrict__ x, const int* __restrict__ ei32,
                            const float* __restrict__ W1, const float* __restrict__ W2,
                            const float* __restrict__ fw) {
    int i = blockIdx.x * 256 + threadIdx.x;
    if (i < N_NODES) g_cnt[i] = 0;
    if (i == 0) {
        int ornz = 0;
#pragma unroll
        for (int k = 0; k < 64; k++) ornz |= ei32[2 * k + 1];
        g_is64 = (ornz == 0) ? 1 : 0;
    }
    if (i < 6 * 16384) {
        int m = i >> 14, t = i & 16383;
        int n = t >> 7, k = t & 127;
        int l = m >> 1;
        const float* src = (m & 1) ? W2 : W1;
        float v = src[l * 16384 + k * 128 + n];
        __nv_bfloat16 h = __float2bfloat16_rn(v);
        g_wthi[m][n * 128 + k] = h;
        g_wtlo[m][n * 128 + k] = __float2bfloat16_rn(v - __bfloat162float(h));
    } else if (i < 6 * 16384 + 128 * 512) {
        int t = i - 6 * 16384;
        int n = t >> 9, k = t & 511;
        float v = fw[k * 128 + n];
        __nv_bfloat16 h = __float2bfloat16_rn(v);
        g_fwthi[n * 512 + k] = h;
        g_fwtlo[n * 512 + k] = __float2bfloat16_rn(v - __bfloat162float(h));
    }
    if (i < NELEM / 8) {
        const float4* xp = (const float4*)x;
        float4 v0 = xp[2 * i], v1 = xp[2 * i + 1];
        float v[8] = {v0.x, v0.y, v0.z, v0.w, v1.x, v1.y, v1.z, v1.w};
        uint4 hp, lp;
        __nv_bfloat162* h2 = (__nv_bfloat162*)&hp;
        __nv_bfloat162* l2 = (__nv_bfloat162*)&lp;
#pragma unroll
        for (int j = 0; j < 4; j++) {
            __nv_bfloat16 h0 = __float2bfloat16_rn(v[2 * j]);
            __nv_bfloat16 h1 = __float2bfloat16_rn(v[2 * j + 1]);
            h2[j].x = h0; h2[j].y = h1;
            l2[j].x = __float2bfloat16_rn(v[2 * j] - __bfloat162float(h0));
            l2[j].y = __float2bfloat16_rn(v[2 * j + 1] - __bfloat162float(h1));
        }
        ((uint4*)g_xhi)[i] = hp;
        ((uint4*)g_xlo)[i] = lp;
    }
}

// ---------------- CSR build (8 edges/thread) ----------------
__global__ void hist_kernel(const int* __restrict__ ei32) {
    int e = (blockIdx.x * 256 + threadIdx.x) * 8;
    if (e >= N_EDGES) return;
    int is64 = g_is64;
    int d[8];
    if (is64) {
#pragma unroll
        for (int q = 0; q < 4; q++) {
            int4 a = *(const int4*)&ei32[2 * (N_EDGES + e) + 4 * q];
            d[2 * q] = a.x; d[2 * q + 1] = a.z;
        }
    } else {
        int4 a = *(const int4*)&ei32[N_EDGES + e];
        int4 b = *(const int4*)&ei32[N_EDGES + e + 4];
        d[0] = a.x; d[1] = a.y; d[2] = a.z; d[3] = a.w;
        d[4] = b.x; d[5] = b.y; d[6] = b.z; d[7] = b.w;
    }
#pragma unroll
    for (int q = 0; q < 8; q++)
        if ((unsigned)d[q] < (unsigned)N_NODES) atomicAdd(&g_cnt[d[q]], 1);
}

__global__ void bsum_kernel() {   // per-block sums; also zeroes g_cnt2
    __shared__ int sh[256];
    int t = threadIdx.x, i = blockIdx.x * 256 + t;
    if (i < N_NODES) g_cnt2[i] = 0;
    sh[t] = (i < N_NODES) ? g_cnt[i] : 0;
    __syncthreads();
#pragma unroll
    for (int off = 128; off > 0; off >>= 1) {
        if (t < off) sh[t] += sh[t + off];
        __syncthreads();
    }
    if (t == 0) g_bsum[blockIdx.x] = sh[0];
}

__global__ void rowptr_kernel() {
    __shared__ int sb[256];
    __shared__ int sh[256];
    int t = threadIdx.x, i = blockIdx.x * 256 + t;
    int bv = (t < NBLK) ? g_bsum[t] : 0;
    sb[t] = bv;
    __syncthreads();
#pragma unroll
    for (int off = 1; off < 256; off <<= 1) {
        int a = (t >= off) ? sb[t - off] : 0;
        __syncthreads();
        sb[t] += a;
        __syncthreads();
    }
    int boff = sb[blockIdx.x] - g_bsum[blockIdx.x];
    if (blockIdx.x == 0 && t == 0) g_rowptr[N_NODES] = sb[255];

    int v = (i < N_NODES) ? g_cnt[i] : 0;
    sh[t] = v;
    __syncthreads();
#pragma unroll
    for (int off = 1; off < 256; off <<= 1) {
        int a = (t >= off) ? sh[t - off] : 0;
        __syncthreads();
        sh[t] += a;
        __syncthreads();
    }
    if (i < N_NODES) g_rowptr[i] = boff + sh[t] - v;
}

__global__ void scatter_kernel(const int* __restrict__ ei32) {
    int e = (blockIdx.x * 256 + threadIdx.x) * 8;
    if (e >= N_EDGES) return;
    int is64 = g_is64;
    int s[8], d[8];
    if (is64) {
#pragma unroll
        for (int q = 0; q < 4; q++) {
            int4 a = *(const int4*)&ei32[2 * e + 4 * q];
            s[2 * q] = a.x; s[2 * q + 1] = a.z;
            int4 c = *(const int4*)&ei32[2 * (N_EDGES + e) + 4 * q];
            d[2 * q] = c.x; d[2 * q + 1] = c.z;
        }
    } else {
        int4 a = *(const int4*)&ei32[e];
        int4 b = *(const int4*)&ei32[e + 4];
        s[0] = a.x; s[1] = a.y; s[2] = a.z; s[3] = a.w;
        s[4] = b.x; s[5] = b.y; s[6] = b.z; s[7] = b.w;
        int4 c = *(const int4*)&ei32[N_EDGES + e];
        int4 f = *(const int4*)&ei32[N_EDGES + e + 4];
        d[0] = c.x; d[1] = c.y; d[2] = c.z; d[3] = c.w;
        d[4] = f.x; d[5] = f.y; d[6] = f.z; d[7] = f.w;
    }
#pragma unroll
    for (int q = 0; q < 8; q++) {
        if ((unsigned)d[q] < (unsigned)N_NODES && (unsigned)s[q] < (unsigned)N_NODES) {
            int pos = g_rowptr[d[q]] + atomicAdd(&g_cnt2[d[q]], 1);
            if ((unsigned)pos < (unsigned)N_EDGES) g_srcs[pos] = s[q];
        }
    }
}

// ---------------- aggregation: t = (1+eps)*h + segsum (hi/lo pairs) ---------
__global__ void agg_kernel(int hsel, const float* __restrict__ eps, int l) {
    const __nv_bfloat16 *hib, *lob;
    sel_hl(hsel, hib, lob);
    int wnode = (blockIdx.x * blockDim.x + threadIdx.x) >> 5;
    int lane = threadIdx.x & 31;
    if (wnode >= N_NODES) return;
    int half = lane >> 4;
    int p = lane & 15;
    const uint4* rows = (const uint4*)(half ? lob : hib);
    float acc[8];
#pragma unroll
    for (int j = 0; j < 8; j++) acc[j] = 0.f;

    int beg = g_rowptr[wnode], end = g_rowptr[wnode + 1];
    int i = beg;
    for (; i + 4 <= end; i += 4) {
        int s0 = g_srcs[i], s1 = g_srcs[i + 1];
        int s2 = g_srcs[i + 2], s3 = g_srcs[i + 3];
        uint4 v0 = rows[s0 * 16 + p];
        uint4 v1 = rows[s1 * 16 + p];
        uint4 v2 = rows[s2 * 16 + p];
        uint4 v3 = rows[s3 * 16 + p];
        const __nv_bfloat162* p0 = (const __nv_bfloat162*)&v0;
        const __nv_bfloat162* p1 = (const __nv_bfloat162*)&v1;
        const __nv_bfloat162* p2 = (const __nv_bfloat162*)&v2;
        const __nv_bfloat162* p3 = (const __nv_bfloat162*)&v3;
#pragma unroll
        for (int j = 0; j < 4; j++) {
            float2 f0 = __bfloat1622float2(p0[j]);
            float2 f1 = __bfloat1622float2(p1[j]);
            float2 f2 = __bfloat1622float2(p2[j]);
            float2 f3 = __bfloat1622float2(p3[j]);
            acc[2 * j]     += (f0.x + f1.x) + (f2.x + f3.x);
            acc[2 * j + 1] += (f0.y + f1.y) + (f2.y + f3.y);
        }
    }
    for (; i < end; i++) {
        uint4 v = rows[g_srcs[i] * 16 + p];
        const __nv_bfloat162* pv = (const __nv_bfloat162*)&v;
#pragma unroll
        for (int j = 0; j < 4; j++) {
            float2 f = __bfloat1622float2(pv[j]);
            acc[2 * j] += f.x;
            acc[2 * j + 1] += f.y;
        }
    }
    float e = 1.0f + eps[l];
    {
        uint4 v = rows[wnode * 16 + p];
        const __nv_bfloat162* pv = (const __nv_bfloat162*)&v;
#pragma unroll
        for (int j = 0; j < 4; j++) {
            float2 f = __bfloat1622float2(pv[j]);
            acc[2 * j] += e * f.x;
            acc[2 * j + 1] += e * f.y;
        }
    }
    float tot[8];
#pragma unroll
    for (int j = 0; j < 8; j++)
        tot[j] = acc[j] + __shfl_xor_sync(0xffffffffu, acc[j], 16);
    uint4 outv;
    __nv_bfloat162* o2 = (__nv_bfloat162*)&outv;
#pragma unroll
    for (int j = 0; j < 4; j++) {
        __nv_bfloat16 h0 = __float2bfloat16_rn(tot[2 * j]);
        __nv_bfloat16 h1 = __float2bfloat16_rn(tot[2 * j + 1]);
        if (half == 0) { o2[j].x = h0; o2[j].y = h1; }
        else {
            o2[j].x = __float2bfloat16_rn(tot[2 * j] - __bfloat162float(h0));
            o2[j].y = __float2bfloat16_rn(tot[2 * j + 1] - __bfloat162float(h1));
        }
    }
    uint4* dst = (uint4*)(half ? g_tlo : g_thi);
    dst[wnode * 16 + p] = outv;
}

// ---------------- tensor-core GEMM machinery ----------------
__device__ __forceinline__ void cp16(unsigned s, const void* g, bool pred) {
    int sz = pred ? 16 : 0;
    asm volatile("cp.async.cg.shared.global [%0], [%1], 16, %2;\n"
                 :: "r"(s), "l"(g), "r"(sz));
}
__device__ __forceinline__ void cp_commit() { asm volatile("cp.async.commit_group;\n"); }
template <int N>
__device__ __forceinline__ void cp_wait() {
    asm volatile("cp.async.wait_group %0;\n" :: "n"(N) : "memory");
}

__device__ __forceinline__ void ldsm4(unsigned* r, unsigned addr) {
    asm volatile("ldmatrix.sync.aligned.m8n8.x4.shared.b16 {%0,%1,%2,%3}, [%4];"
                 : "=r"(r[0]), "=r"(r[1]), "=r"(r[2]), "=r"(r[3]) : "r"(addr));
}
__device__ __forceinline__ void mma_bf16(float* c, const unsigned* a, const unsigned* b) {
    asm volatile(
        "mma.sync.aligned.m16n8k16.row.col.f32.bf16.bf16.f32 "
        "{%0,%1,%2,%3},{%4,%5,%6,%7},{%8,%9},{%0,%1,%2,%3};"
        : "+f"(c[0]), "+f"(c[1]), "+f"(c[2]), "+f"(c[3])
        : "r"(a[0]), "r"(a[1]), "r"(a[2]), "r"(a[3]), "r"(b[0]), "r"(b[1]));
}
__device__ __forceinline__ void store_hl(__nv_bfloat16* Ohi, __nv_bfloat16* Olo,
                                         long long off, float v0, float v1) {
    __nv_bfloat16 h0 = __float2bfloat16_rn(v0), h1 = __float2bfloat16_rn(v1);
    __nv_bfloat162 hp; hp.x = h0; hp.y = h1;
    *(__nv_bfloat162*)(Ohi + off) = hp;
    __nv_bfloat162 lp;
    lp.x = __float2bfloat16_rn(v0 - __bfloat162float(h0));
    lp.y = __float2bfloat16_rn(v1 - __bfloat162float(h1));
    *(__nv_bfloat162*)(Olo + off) = lp;
}

// 4-stage dynamic smem: per stage mats {Ahi, Alo, Whi, Wlo}, each 128 rows x 24 bf16
#define MAT_BYTES 6144u
#define NSTAGE 4
#define SMEM_BYTES (NSTAGE * 4 * MAT_BYTES)   // 98304

__device__ __forceinline__ void mma_chunk(unsigned mbase, int aoff0, int aoff1,
                                          const int* woff, float acc[2][8][4]) {
    unsigned ah[2][4], al[2][4];
    ldsm4(ah[0], mbase + 0 * MAT_BYTES + aoff0);
    ldsm4(ah[1], mbase + 0 * MAT_BYTES + aoff1);
    ldsm4(al[0], mbase + 1 * MAT_BYTES + aoff0);
    ldsm4(al[1], mbase + 1 * MAT_BYTES + aoff1);
#pragma unroll
    for (int ng = 0; ng < 4; ng++) {
        unsigned bh[4], bl[4];
        ldsm4(bh, mbase + 2 * MAT_BYTES + woff[ng]);
        ldsm4(bl, mbase + 3 * MAT_BYTES + woff[ng]);
#pragma unroll
        for (int mi = 0; mi < 2; mi++)
#pragma unroll
            for (int ns = 0; ns < 2; ns++) {
                float* C = acc[mi][ng * 2 + ns];
                mma_bf16(C, ah[mi], &bh[ns * 2]);
                mma_bf16(C, ah[mi], &bl[ns * 2]);
                mma_bf16(C, al[mi], &bh[ns * 2]);
            }
    }
}

// ---------------- layer GEMM: out = relu(A @ W + bias), K=128, BM=128 --------
__global__ void __launch_bounds__(256, 2)
mma_gemm_kernel(int a_sel, int w_idx, const float* __restrict__ bias, int o_sel) {
    extern __shared__ __nv_bfloat16 dynsm[];
    const unsigned base = (unsigned)__cvta_generic_to_shared(dynsm);

    const __nv_bfloat16 *Ahi, *Alo;
    sel_hl(a_sel, Ahi, Alo);
    __nv_bfloat16 *Ohi, *Olo;
    sel_out(o_sel, Ohi, Olo);
    const __nv_bfloat16* Whi = g_wthi[w_idx];
    const __nv_bfloat16* Wlo = g_wtlo[w_idx];

    const int tid = threadIdx.x, lane = tid & 31, w = tid >> 5;
    const int wm = w & 3, wn = w >> 2;
    const int rowBase = blockIdx.x * 128;
    const int g = lane >> 3, r = lane & 7;

    const int aoff0 = (wm * 32 + 0 + (g & 1) * 8 + r) * 48 + (g >> 1) * 16;
    const int aoff1 = (wm * 32 + 16 + (g & 1) * 8 + r) * 48 + (g >> 1) * 16;
    int woff[4];
#pragma unroll
    for (int ng = 0; ng < 4; ng++)
        woff[ng] = (wn * 64 + ng * 16 + (g >> 1) * 8 + r) * 48 + (g & 1) * 16;

    float acc[2][8][4];
#pragma unroll
    for (int i = 0; i < 2; i++)
#pragma unroll
        for (int j = 0; j < 8; j++)
#pragma unroll
            for (int q = 0; q < 4; q++) acc[i][j][q] = 0.f;

    const int crow = tid >> 1, chalf = tid & 1;
    const unsigned dsto = (unsigned)(crow * 48 + chalf * 16);
    const bool aok = (rowBase + crow) < N_NODES;
    const long long arow = (long long)(rowBase + crow) * 128;

#pragma unroll
    for (int pc = 0; pc < 3; pc++) {
        unsigned mb = base + (unsigned)pc * 4 * MAT_BYTES;
        int kb = pc * 16 + chalf * 8;
        cp16(mb + 0 * MAT_BYTES + dsto, Ahi + arow + kb, aok);
        cp16(mb + 1 * MAT_BYTES + dsto, Alo + arow + kb, aok);
        cp16(mb + 2 * MAT_BYTES + dsto, Whi + crow * 128 + kb, true);
        cp16(mb + 3 * MAT_BYTES + dsto, Wlo + crow * 128 + kb, true);
        cp_commit();
    }

#pragma unroll
    for (int c = 0; c < 8; c++) {
        if (c < 6) cp_wait<2>();
        else if (c == 6) cp_wait<1>();
        else cp_wait<0>();
        __syncthreads();
        // issue loads for stage c+3 BEFORE compute: extra chunk of latency cover
        if (c + 3 < 8) {
            unsigned mb = base + (unsigned)((c + 3) & 3) * 4 * MAT_BYTES;
            int kb = (c + 3) * 16 + chalf * 8;
            cp16(mb + 0 * MAT_BYTES + dsto, Ahi + arow + kb, aok);
            cp16(mb + 1 * MAT_BYTES + dsto, Alo + arow + kb, aok);
            cp16(mb + 2 * MAT_BYTES + dsto, Whi + crow * 128 + kb, true);
            cp16(mb + 3 * MAT_BYTES + dsto, Wlo + crow * 128 + kb, true);
            cp_commit();
        }
        mma_chunk(base + (unsigned)(c & 3) * 4 * MAT_BYTES, aoff0, aoff1, woff, acc);
    }

#pragma unroll
    for (int ni = 0; ni < 8; ni++) {
        int n0 = wn * 64 + ni * 8 + 2 * (lane & 3);
        float2 bv = *(const float2*)&bias[n0];
#pragma unroll
        for (int mi = 0; mi < 2; mi++) {
            int r0 = rowBase + wm * 32 + mi * 16 + (lane >> 2);
            float* C = acc[mi][ni];
            float v0 = fmaxf(C[0] + bv.x, 0.f), v1 = fmaxf(C[1] + bv.y, 0.f);
            float v2 = fmaxf(C[2] + bv.x, 0.f), v3 = fmaxf(C[3] + bv.y, 0.f);
            if (r0 < N_NODES) store_hl(Ohi, Olo, (long long)r0 * 128 + n0, v0, v1);
            if (r0 + 8 < N_NODES) store_hl(Ohi, Olo, (long long)(r0 + 8) * 128 + n0, v2, v3);
        }
    }
}

// ---------------- final GEMM: out = concat(x,h0,h1,h2) @ fw + fb, K=512 ------
__device__ __forceinline__ void final_src(int s, const __nv_bfloat16*& hi,
                                          const __nv_bfloat16*& lo) {
    switch (s) {
        case 0: hi = g_xhi; lo = g_xlo; break;
        case 1: hi = g_hhi[0]; lo = g_hlo[0]; break;
        case 2: hi = g_hhi[1]; lo = g_hlo[1]; break;
        default: hi = g_hhi[2]; lo = g_hlo[2]; break;
    }
}

__global__ void __launch_bounds__(256, 2)
final_gemm_kernel(const float* __restrict__ fb, float* __restrict__ out) {
    extern __shared__ __nv_bfloat16 dynsm[];
    const unsigned base = (unsigned)__cvta_generic_to_shared(dynsm);

    const int tid = threadIdx.x, lane = tid & 31, w = tid >> 5;
    const int wm = w & 3, wn = w >> 2;
    const int rowBase = blockIdx.x * 128;
    const int g = lane >> 3, r = lane & 7;

    const int aoff0 = (wm * 32 + 0 + (g & 1) * 8 + r) * 48 + (g >> 1) * 16;
    const int aoff1 = (wm * 32 + 16 + (g & 1) * 8 + r) * 48 + (g >> 1) * 16;
    int woff[4];
#pragma unroll
    for (int ng = 0; ng < 4; ng++)
        woff[ng] = (wn * 64 + ng * 16 + (g >> 1) * 8 + r) * 48 + (g & 1) * 16;

    float acc[2][8][4];
#pragma unroll
    for (int i = 0; i < 2; i++)
#pragma unroll
        for (int j = 0; j < 8; j++)
#pragma unroll
            for (int q = 0; q < 4; q++) acc[i][j][q] = 0.f;

    const int crow = tid >> 1, chalf = tid & 1;
    const unsigned dsto = (unsigned)(crow * 48 + chalf * 16);
    const bool aok = (rowBase + crow) < N_NODES;
    const long long arow = (long long)(rowBase + crow) * 128;

#pragma unroll
    for (int pc = 0; pc < 3; pc++) {
        const __nv_bfloat16 *shi, *slo;
        final_src(pc >> 3, shi, slo);
        unsigned mb = base + (unsigned)pc * 4 * MAT_BYTES;
        int ka = (pc & 7) * 16 + chalf * 8;
        int kw = pc * 16 + chalf * 8;
        cp16(mb + 0 * MAT_BYTES + dsto, shi + arow + ka, aok);
        cp16(mb + 1 * MAT_BYTES + dsto, slo + arow + ka, aok);
        cp16(mb + 2 * MAT_BYTES + dsto, g_fwthi + crow * 512 + kw, true);
        cp16(mb + 3 * MAT_BYTES + dsto, g_fwtlo + crow * 512 + kw, true);
        cp_commit();
    }

    for (int c = 0; c < 32; c++) {
        if (c < 30) cp_wait<2>();
        else if (c == 30) cp_wait<1>();
        else cp_wait<0>();
        __syncthreads();
        if (c + 3 < 32) {
            int cn = c + 3;
            const __nv_bfloat16 *shi, *slo;
            final_src(cn >> 3, shi, slo);
            unsigned mb = base + (unsigned)(cn & 3) * 4 * MAT_BYTES;
            int ka = (cn & 7) * 16 + chalf * 8;
            int kw = cn * 16 + chalf * 8;
            cp16(mb + 0 * MAT_BYTES + dsto, shi + arow + ka, aok);
            cp16(mb + 1 * MAT_BYTES + dsto, slo + arow + ka, aok);
            cp16(mb + 2 * MAT_BYTES + dsto, g_fwthi + crow * 512 + kw, true);
            cp16(mb + 3 * MAT_BYTES + dsto, g_fwtlo + crow * 512 + kw, true);
            cp_commit();
        }
        mma_chunk(base + (unsigned)(c & 3) * 4 * MAT_BYTES, aoff0, aoff1, woff, acc);
    }

#pragma unroll
    for (int ni = 0; ni < 8; ni++) {
        int n0 = wn * 64 + ni * 8 + 2 * (lane & 3);
        float2 bv = *(const float2*)&fb[n0];
#pragma unroll
        for (int mi = 0; mi < 2; mi++) {
            int r0 = rowBase + wm * 32 + mi * 16 + (lane >> 2);
            float* C = acc[mi][ni];
            if (r0 < N_NODES) {
                float2 o = make_float2(C[0] + bv.x, C[1] + bv.y);
                *(float2*)&out[(long long)r0 * 128 + n0] = o;
            }
            if (r0 + 8 < N_NODES) {
                float2 o = make_float2(C[2] + bv.x, C[3] + bv.y);
                *(float2*)&out[(long long)(r0 + 8) * 128 + n0] = o;
            }
        }
    }
}

// ---------------- launch ----------------
extern "C" void kernel_launch(void* const* d_in, const int* in_sizes, int n_in,
                              void* d_out, int out_size) {
    const float* x   = (const float*)d_in[0];
    const int*   ei  = (const int*)d_in[1];
    const float* W1  = (const float*)d_in[2];
    const float* b1  = (const float*)d_in[3];
    const float* W2  = (const float*)d_in[4];
    const float* b2  = (const float*)d_in[5];
    const float* eps = (const float*)d_in[6];
    const float* fw  = (const float*)d_in[7];
    const float* fb  = (const float*)d_in[8];
    float* out = (float*)d_out;

    cudaFuncSetAttribute(mma_gemm_kernel,
                         cudaFuncAttributeMaxDynamicSharedMemorySize, SMEM_BYTES);
    cudaFuncSetAttribute(final_gemm_kernel,
                         cudaFuncAttributeMaxDynamicSharedMemorySize, SMEM_BYTES);

    const int PB = (NELEM / 8 + 255) / 256;          // 3125
    const int EB8 = (N_EDGES / 8 + 255) / 256;       // 313
    const int GB = (N_NODES + 127) / 128;            // 391
    const int AB = (N_NODES * 32 + 255) / 256;       // warp per node

    // fused prep + CSR build
    prep_kernel<<<PB, 256>>>(x, ei, W1, W2, fw);
    hist_kernel<<<EB8, 256>>>(ei);
    bsum_kernel<<<NBLK, 256>>>();
    rowptr_kernel<<<NBLK, 256>>>();
    scatter_kernel<<<EB8, 256>>>(ei);

    // 3 GIN layers
    int hin[3]  = { SEL_X, SEL_H0, SEL_H1 };
    int hout[3] = { SEL_H0, SEL_H1, SEL_H2 };
    for (int l = 0; l < 3; l++) {
        agg_kernel<<<AB, 256>>>(hin[l], eps, l);
        mma_gemm_kernel<<<GB, 256, SMEM_BYTES>>>(SEL_T, 2 * l,     b1 + l * 128, SEL_Z);
        mma_gemm_kernel<<<GB, 256, SMEM_BYTES>>>(SEL_Z, 2 * l + 1, b2 + l * 128, hout[l]);
    }
    final_gemm_kernel<<<GB, 256, SMEM_BYTES>>>(fb, out);
}

// round 15
// speedup vs baseline: 1.2013x; 1.0152x over previous
#include <cuda_runtime.h>
#include <cuda_bf16.h>

#define N_NODES 50000
#define N_EDGES 640000
#define NELEM (N_NODES * 128)
#define NBLK 196

// ---------------- scratch (device globals) ----------------
__device__ __align__(16) __nv_bfloat16 g_xhi[NELEM], g_xlo[NELEM];
__device__ __align__(16) __nv_bfloat16 g_thi[NELEM], g_tlo[NELEM];
__device__ __align__(16) __nv_bfloat16 g_zhi[NELEM], g_zlo[NELEM];
__device__ __align__(16) __nv_bfloat16 g_hhi[3][NELEM], g_hlo[3][NELEM];
__device__ __align__(16) __nv_bfloat16 g_wthi[6][128 * 128], g_wtlo[6][128 * 128];
__device__ __align__(16) __nv_bfloat16 g_fwthi[128 * 512], g_fwtlo[128 * 512];
__device__ int g_rowptr[N_NODES + 1], g_cnt[N_NODES], g_cnt2[N_NODES], g_srcs[N_EDGES];
__device__ int g_is64, g_bsum[256];

#define SEL_X 0
#define SEL_T 1
#define SEL_Z 2
#define SEL_H0 3
#define SEL_H1 4
#define SEL_H2 5

__device__ __forceinline__ void sel_hl(int s, const __nv_bfloat16*& hi,
                                       const __nv_bfloat16*& lo) {
    switch (s) {
        case SEL_X: hi = g_xhi; lo = g_xlo; break;
        case SEL_T: hi = g_thi; lo = g_tlo; break;
        case SEL_Z: hi = g_zhi; lo = g_zlo; break;
        case SEL_H0: hi = g_hhi[0]; lo = g_hlo[0]; break;
        case SEL_H1: hi = g_hhi[1]; lo = g_hlo[1]; break;
        default:     hi = g_hhi[2]; lo = g_hlo[2]; break;
    }
}
__device__ __forceinline__ void sel_out(int s, __nv_bfloat16*& hi, __nv_bfloat16*& lo) {
    switch (s) {
        case SEL_T: hi = g_thi; lo = g_tlo; break;
        case SEL_Z: hi = g_zhi; lo = g_zlo; break;
        case SEL_H0: hi = g_hhi[0]; lo = g_hlo[0]; break;
        case SEL_H1: hi = g_hhi[1]; lo = g_hlo[1]; break;
        default:     hi = g_hhi[2]; lo = g_hlo[2]; break;
    }
}

// ---------------- fused prep: zero cnt + detect dtype + split x + split W ----
__global__ void prep_kernel(const float* __restrict__ x, const int* __restrict__ ei32,
                            const float* __restrict__ W1, const float* __restrict__ W2,
                            const float* __restrict__ fw) {
    int i = blockIdx.x * 256 + threadIdx.x;
    if (i < N_NODES) g_cnt[i] = 0;
    if (i == 0) {
        int ornz = 0;
#pragma unroll
        for (int k = 0; k < 64; k++) ornz |= ei32[2 * k + 1];
        g_is64 = (ornz == 0) ? 1 : 0;
    }
    if (i < 6 * 16384) {
        int m = i >> 14, t = i & 16383;
        int n = t >> 7, k = t & 127;
        int l = m >> 1;
        const float* src = (m & 1) ? W2 : W1;
        float v = src[l * 16384 + k * 128 + n];
        __nv_bfloat16 h = __float2bfloat16_rn(v);
        g_wthi[m][n * 128 + k] = h;
        g_wtlo[m][n * 128 + k] = __float2bfloat16_rn(v - __bfloat162float(h));
    } else if (i < 6 * 16384 + 128 * 512) {
        int t = i - 6 * 16384;
        int n = t >> 9, k = t & 511;
        float v = fw[k * 128 + n];
        __nv_bfloat16 h = __float2bfloat16_rn(v);
        g_fwthi[n * 512 + k] = h;
        g_fwtlo[n * 512 + k] = __float2bfloat16_rn(v - __bfloat162float(h));
    }
    if (i < NELEM / 8) {
        const float4* xp = (const float4*)x;
        float4 v0 = xp[2 * i], v1 = xp[2 * i + 1];
        float v[8] = {v0.x, v0.y, v0.z, v0.w, v1.x, v1.y, v1.z, v1.w};
        uint4 hp, lp;
        __nv_bfloat162* h2 = (__nv_bfloat162*)&hp;
        __nv_bfloat162* l2 = (__nv_bfloat162*)&lp;
#pragma unroll
        for (int j = 0; j < 4; j++) {
            __nv_bfloat16 h0 = __float2bfloat16_rn(v[2 * j]);
            __nv_bfloat16 h1 = __float2bfloat16_rn(v[2 * j + 1]);
            h2[j].x = h0; h2[j].y = h1;
            l2[j].x = __float2bfloat16_rn(v[2 * j] - __bfloat162float(h0));
            l2[j].y = __float2bfloat16_rn(v[2 * j + 1] - __bfloat162float(h1));
        }
        ((uint4*)g_xhi)[i] = hp;
        ((uint4*)g_xlo)[i] = lp;
    }
}

// ---------------- CSR build (8 edges/thread) ----------------
__global__ void hist_kernel(const int* __restrict__ ei32) {
    int e = (blockIdx.x * 256 + threadIdx.x) * 8;
    if (e >= N_EDGES) return;
    int is64 = g_is64;
    int d[8];
    if (is64) {
#pragma unroll
        for (int q = 0; q < 4; q++) {
            int4 a = *(const int4*)&ei32[2 * (N_EDGES + e) + 4 * q];
            d[2 * q] = a.x; d[2 * q + 1] = a.z;
        }
    } else {
        int4 a = *(const int4*)&ei32[N_EDGES + e];
        int4 b = *(const int4*)&ei32[N_EDGES + e + 4];
        d[0] = a.x; d[1] = a.y; d[2] = a.z; d[3] = a.w;
        d[4] = b.x; d[5] = b.y; d[6] = b.z; d[7] = b.w;
    }
#pragma unroll
    for (int q = 0; q < 8; q++)
        if ((unsigned)d[q] < (unsigned)N_NODES) atomicAdd(&g_cnt[d[q]], 1);
}

__global__ void bsum_kernel() {   // per-block sums (warp-shuffle); also zeroes g_cnt2
    __shared__ int warpsum[8];
    int t = threadIdx.x, i = blockIdx.x * 256 + t;
    if (i < N_NODES) g_cnt2[i] = 0;
    int v = (i < N_NODES) ? g_cnt[i] : 0;
#pragma unroll
    for (int off = 16; off > 0; off >>= 1)
        v += __shfl_down_sync(0xffffffffu, v, off);
    if ((t & 31) == 0) warpsum[t >> 5] = v;
    __syncthreads();
    if (t < 8) {
        int s = warpsum[t];
#pragma unroll
        for (int off = 4; off > 0; off >>= 1)
            s += __shfl_down_sync(0xffu, s, off);
        if (t == 0) g_bsum[blockIdx.x] = s;
    }
}

__global__ void rowptr_kernel() {
    __shared__ int sb[256];
    __shared__ int sh[256];
    int t = threadIdx.x, i = blockIdx.x * 256 + t;
    int bv = (t < NBLK) ? g_bsum[t] : 0;
    sb[t] = bv;
    __syncthreads();
#pragma unroll
    for (int off = 1; off < 256; off <<= 1) {
        int a = (t >= off) ? sb[t - off] : 0;
        __syncthreads();
        sb[t] += a;
        __syncthreads();
    }
    int boff = sb[blockIdx.x] - g_bsum[blockIdx.x];
    if (blockIdx.x == 0 && t == 0) g_rowptr[N_NODES] = sb[255];

    int v = (i < N_NODES) ? g_cnt[i] : 0;
    sh[t] = v;
    __syncthreads();
#pragma unroll
    for (int off = 1; off < 256; off <<= 1) {
        int a = (t >= off) ? sh[t - off] : 0;
        __syncthreads();
        sh[t] += a;
        __syncthreads();
    }
    if (i < N_NODES) g_rowptr[i] = boff + sh[t] - v;
}

__global__ void scatter_kernel(const int* __restrict__ ei32) {
    int e = (blockIdx.x * 256 + threadIdx.x) * 8;
    if (e >= N_EDGES) return;
    int is64 = g_is64;
    int s[8], d[8];
    if (is64) {
#pragma unroll
        for (int q = 0; q < 4; q++) {
            int4 a = *(const int4*)&ei32[2 * e + 4 * q];
            s[2 * q] = a.x; s[2 * q + 1] = a.z;
            int4 c = *(const int4*)&ei32[2 * (N_EDGES + e) + 4 * q];
            d[2 * q] = c.x; d[2 * q + 1] = c.z;
        }
    } else {
        int4 a = *(const int4*)&ei32[e];
        int4 b = *(const int4*)&ei32[e + 4];
        s[0] = a.x; s[1] = a.y; s[2] = a.z; s[3] = a.w;
        s[4] = b.x; s[5] = b.y; s[6] = b.z; s[7] = b.w;
        int4 c = *(const int4*)&ei32[N_EDGES + e];
        int4 f = *(const int4*)&ei32[N_EDGES + e + 4];
        d[0] = c.x; d[1] = c.y; d[2] = c.z; d[3] = c.w;
        d[4] = f.x; d[5] = f.y; d[6] = f.z; d[7] = f.w;
    }
#pragma unroll
    for (int q = 0; q < 8; q++) {
        if ((unsigned)d[q] < (unsigned)N_NODES && (unsigned)s[q] < (unsigned)N_NODES) {
            int pos = g_rowptr[d[q]] + atomicAdd(&g_cnt2[d[q]], 1);
            if ((unsigned)pos < (unsigned)N_EDGES) g_srcs[pos] = s[q];
        }
    }
}

// ---------------- aggregation: t = (1+eps)*h + segsum (hi/lo pairs) ---------
__global__ void agg_kernel(int hsel, const float* __restrict__ eps, int l) {
    const __nv_bfloat16 *hib, *lob;
    sel_hl(hsel, hib, lob);
    int wnode = (blockIdx.x * blockDim.x + threadIdx.x) >> 5;
    int lane = threadIdx.x & 31;
    if (wnode >= N_NODES) return;
    int half = lane >> 4;
    int p = lane & 15;
    const uint4* rows = (const uint4*)(half ? lob : hib);
    float acc[8];
#pragma unroll
    for (int j = 0; j < 8; j++) acc[j] = 0.f;

    int beg = g_rowptr[wnode], end = g_rowptr[wnode + 1];
    int i = beg;
    for (; i + 4 <= end; i += 4) {
        int s0 = g_srcs[i], s1 = g_srcs[i + 1];
        int s2 = g_srcs[i + 2], s3 = g_srcs[i + 3];
        uint4 v0 = rows[s0 * 16 + p];
        uint4 v1 = rows[s1 * 16 + p];
        uint4 v2 = rows[s2 * 16 + p];
        uint4 v3 = rows[s3 * 16 + p];
        const __nv_bfloat162* p0 = (const __nv_bfloat162*)&v0;
        const __nv_bfloat162* p1 = (const __nv_bfloat162*)&v1;
        const __nv_bfloat162* p2 = (const __nv_bfloat162*)&v2;
        const __nv_bfloat162* p3 = (const __nv_bfloat162*)&v3;
#pragma unroll
        for (int j = 0; j < 4; j++) {
            float2 f0 = __bfloat1622float2(p0[j]);
            float2 f1 = __bfloat1622float2(p1[j]);
            float2 f2 = __bfloat1622float2(p2[j]);
            float2 f3 = __bfloat1622float2(p3[j]);
            acc[2 * j]     += (f0.x + f1.x) + (f2.x + f3.x);
            acc[2 * j + 1] += (f0.y + f1.y) + (f2.y + f3.y);
        }
    }
    for (; i < end; i++) {
        uint4 v = rows[g_srcs[i] * 16 + p];
        const __nv_bfloat162* pv = (const __nv_bfloat162*)&v;
#pragma unroll
        for (int j = 0; j < 4; j++) {
            float2 f = __bfloat1622float2(pv[j]);
            acc[2 * j] += f.x;
            acc[2 * j + 1] += f.y;
        }
    }
    float e = 1.0f + eps[l];
    {
        uint4 v = rows[wnode * 16 + p];
        const __nv_bfloat162* pv = (const __nv_bfloat162*)&v;
#pragma unroll
        for (int j = 0; j < 4; j++) {
            float2 f = __bfloat1622float2(pv[j]);
            acc[2 * j] += e * f.x;
            acc[2 * j + 1] += e * f.y;
        }
    }
    float tot[8];
#pragma unroll
    for (int j = 0; j < 8; j++)
        tot[j] = acc[j] + __shfl_xor_sync(0xffffffffu, acc[j], 16);
    uint4 outv;
    __nv_bfloat162* o2 = (__nv_bfloat162*)&outv;
#pragma unroll
    for (int j = 0; j < 4; j++) {
        __nv_bfloat16 h0 = __float2bfloat16_rn(tot[2 * j]);
        __nv_bfloat16 h1 = __float2bfloat16_rn(tot[2 * j + 1]);
        if (half == 0) { o2[j].x = h0; o2[j].y = h1; }
        else {
            o2[j].x = __float2bfloat16_rn(tot[2 * j] - __bfloat162float(h0));
            o2[j].y = __float2bfloat16_rn(tot[2 * j + 1] - __bfloat162float(h1));
        }
    }
    uint4* dst = (uint4*)(half ? g_tlo : g_thi);
    dst[wnode * 16 + p] = outv;
}

// ---------------- tensor-core GEMM machinery ----------------
__device__ __forceinline__ void cp16(unsigned s, const void* g, bool pred) {
    int sz = pred ? 16 : 0;
    asm volatile("cp.async.cg.shared.global [%0], [%1], 16, %2;\n"
                 :: "r"(s), "l"(g), "r"(sz));
}
__device__ __forceinline__ void cp_commit() { asm volatile("cp.async.commit_group;\n"); }
template <int N>
__device__ __forceinline__ void cp_wait() {
    asm volatile("cp.async.wait_group %0;\n" :: "n"(N) : "memory");
}

__device__ __forceinline__ void ldsm4(unsigned* r, unsigned addr) {
    asm volatile("ldmatrix.sync.aligned.m8n8.x4.shared.b16 {%0,%1,%2,%3}, [%4];"
                 : "=r"(r[0]), "=r"(r[1]), "=r"(r[2]), "=r"(r[3]) : "r"(addr));
}
__device__ __forceinline__ void mma_bf16(float* c, const unsigned* a, const unsigned* b) {
    asm volatile(
        "mma.sync.aligned.m16n8k16.row.col.f32.bf16.bf16.f32 "
        "{%0,%1,%2,%3},{%4,%5,%6,%7},{%8,%9},{%0,%1,%2,%3};"
        : "+f"(c[0]), "+f"(c[1]), "+f"(c[2]), "+f"(c[3])
        : "r"(a[0]), "r"(a[1]), "r"(a[2]), "r"(a[3]), "r"(b[0]), "r"(b[1]));
}
__device__ __forceinline__ void store_hl(__nv_bfloat16* Ohi, __nv_bfloat16* Olo,
                                         long long off, float v0, float v1) {
    __nv_bfloat16 h0 = __float2bfloat16_rn(v0), h1 = __float2bfloat16_rn(v1);
    __nv_bfloat162 hp; hp.x = h0; hp.y = h1;
    *(__nv_bfloat162*)(Ohi + off) = hp;
    __nv_bfloat162 lp;
    lp.x = __float2bfloat16_rn(v0 - __bfloat162float(h0));
    lp.y = __float2bfloat16_rn(v1 - __bfloat162float(h1));
    *(__nv_bfloat162*)(Olo + off) = lp;
}

// 4-stage dynamic smem: per stage mats {Ahi, Alo, Whi, Wlo}, each 128 rows x 24 bf16
#define MAT_BYTES 6144u
#define NSTAGE 4
#define SMEM_BYTES (NSTAGE * 4 * MAT_BYTES)   // 98304

__device__ __forceinline__ void mma_chunk(unsigned mbase, int aoff0, int aoff1,
                                          const int* woff, float acc[2][8][4]) {
    unsigned ah[2][4], al[2][4];
    ldsm4(ah[0], mbase + 0 * MAT_BYTES + aoff0);
    ldsm4(ah[1], mbase + 0 * MAT_BYTES + aoff1);
    ldsm4(al[0], mbase + 1 * MAT_BYTES + aoff0);
    ldsm4(al[1], mbase + 1 * MAT_BYTES + aoff1);
#pragma unroll
    for (int ng = 0; ng < 4; ng++) {
        unsigned bh[4], bl[4];
        ldsm4(bh, mbase + 2 * MAT_BYTES + woff[ng]);
        ldsm4(bl, mbase + 3 * MAT_BYTES + woff[ng]);
#pragma unroll
        for (int mi = 0; mi < 2; mi++)
#pragma unroll
            for (int ns = 0; ns < 2; ns++) {
                float* C = acc[mi][ng * 2 + ns];
                mma_bf16(C, ah[mi], &bh[ns * 2]);
                mma_bf16(C, ah[mi], &bl[ns * 2]);
                mma_bf16(C, al[mi], &bh[ns * 2]);
            }
    }
}

// ---------------- layer GEMM: out = relu(A @ W + bias), K=128, BM=128 --------
__global__ void __launch_bounds__(256, 2)
mma_gemm_kernel(int a_sel, int w_idx, const float* __restrict__ bias, int o_sel) {
    extern __shared__ __nv_bfloat16 dynsm[];
    const unsigned base = (unsigned)__cvta_generic_to_shared(dynsm);

    const __nv_bfloat16 *Ahi, *Alo;
    sel_hl(a_sel, Ahi, Alo);
    __nv_bfloat16 *Ohi, *Olo;
    sel_out(o_sel, Ohi, Olo);
    const __nv_bfloat16* Whi = g_wthi[w_idx];
    const __nv_bfloat16* Wlo = g_wtlo[w_idx];

    const int tid = threadIdx.x, lane = tid & 31, w = tid >> 5;
    const int wm = w & 3, wn = w >> 2;
    const int rowBase = blockIdx.x * 128;
    const int g = lane >> 3, r = lane & 7;

    const int aoff0 = (wm * 32 + 0 + (g & 1) * 8 + r) * 48 + (g >> 1) * 16;
    const int aoff1 = (wm * 32 + 16 + (g & 1) * 8 + r) * 48 + (g >> 1) * 16;
    int woff[4];
#pragma unroll
    for (int ng = 0; ng < 4; ng++)
        woff[ng] = (wn * 64 + ng * 16 + (g >> 1) * 8 + r) * 48 + (g & 1) * 16;

    float acc[2][8][4];
#pragma unroll
    for (int i = 0; i < 2; i++)
#pragma unroll
        for (int j = 0; j < 8; j++)
#pragma unroll
            for (int q = 0; q < 4; q++) acc[i][j][q] = 0.f;

    const int crow = tid >> 1, chalf = tid & 1;
    const unsigned dsto = (unsigned)(crow * 48 + chalf * 16);
    const bool aok = (rowBase + crow) < N_NODES;
    const long long arow = (long long)(rowBase + crow) * 128;

#pragma unroll
    for (int pc = 0; pc < 3; pc++) {
        unsigned mb = base + (unsigned)pc * 4 * MAT_BYTES;
        int kb = pc * 16 + chalf * 8;
        cp16(mb + 0 * MAT_BYTES + dsto, Ahi + arow + kb, aok);
        cp16(mb + 1 * MAT_BYTES + dsto, Alo + arow + kb, aok);
        cp16(mb + 2 * MAT_BYTES + dsto, Whi + crow * 128 + kb, true);
        cp16(mb + 3 * MAT_BYTES + dsto, Wlo + crow * 128 + kb, true);
        cp_commit();
    }

#pragma unroll
    for (int c = 0; c < 8; c++) {
        if (c < 6) cp_wait<2>();
        else if (c == 6) cp_wait<1>();
        else cp_wait<0>();
        __syncthreads();
        mma_chunk(base + (unsigned)(c & 3) * 4 * MAT_BYTES, aoff0, aoff1, woff, acc);
        if (c + 3 < 8) {
            unsigned mb = base + (unsigned)((c + 3) & 3) * 4 * MAT_BYTES;
            int kb = (c + 3) * 16 + chalf * 8;
            cp16(mb + 0 * MAT_BYTES + dsto, Ahi + arow + kb, aok);
            cp16(mb + 1 * MAT_BYTES + dsto, Alo + arow + kb, aok);
            cp16(mb + 2 * MAT_BYTES + dsto, Whi + crow * 128 + kb, true);
            cp16(mb + 3 * MAT_BYTES + dsto, Wlo + crow * 128 + kb, true);
            cp_commit();
        }
    }

#pragma unroll
    for (int ni = 0; ni < 8; ni++) {
        int n0 = wn * 64 + ni * 8 + 2 * (lane & 3);
        float2 bv = *(const float2*)&bias[n0];
#pragma unroll
        for (int mi = 0; mi < 2; mi++) {
            int r0 = rowBase + wm * 32 + mi * 16 + (lane >> 2);
            float* C = acc[mi][ni];
            float v0 = fmaxf(C[0] + bv.x, 0.f), v1 = fmaxf(C[1] + bv.y, 0.f);
            float v2 = fmaxf(C[2] + bv.x, 0.f), v3 = fmaxf(C[3] + bv.y, 0.f);
            if (r0 < N_NODES) store_hl(Ohi, Olo, (long long)r0 * 128 + n0, v0, v1);
            if (r0 + 8 < N_NODES) store_hl(Ohi, Olo, (long long)(r0 + 8) * 128 + n0, v2, v3);
        }
    }
}

// ---------------- final GEMM: out = concat(x,h0,h1,h2) @ fw + fb, K=512 ------
__device__ __forceinline__ void final_src(int s, const __nv_bfloat16*& hi,
                                          const __nv_bfloat16*& lo) {
    switch (s) {
        case 0: hi = g_xhi; lo = g_xlo; break;
        case 1: hi = g_hhi[0]; lo = g_hlo[0]; break;
        case 2: hi = g_hhi[1]; lo = g_hlo[1]; break;
        default: hi = g_hhi[2]; lo = g_hlo[2]; break;
    }
}

__global__ void __launch_bounds__(256, 2)
final_gemm_kernel(const float* __restrict__ fb, float* __restrict__ out) {
    extern __shared__ __nv_bfloat16 dynsm[];
    const unsigned base = (unsigned)__cvta_generic_to_shared(dynsm);

    const int tid = threadIdx.x, lane = tid & 31, w = tid >> 5;
    const int wm = w & 3, wn = w >> 2;
    const int rowBase = blockIdx.x * 128;
    const int g = lane >> 3, r = lane & 7;

    const int aoff0 = (wm * 32 + 0 + (g & 1) * 8 + r) * 48 + (g >> 1) * 16;
    const int aoff1 = (wm * 32 + 16 + (g & 1) * 8 + r) * 48 + (g >> 1) * 16;
    int woff[4];
#pragma unroll
    for (int ng = 0; ng < 4; ng++)
        woff[ng] = (wn * 64 + ng * 16 + (g >> 1) * 8 + r) * 48 + (g & 1) * 16;

    float acc[2][8][4];
#pragma unroll
    for (int i = 0; i < 2; i++)
#pragma unroll
        for (int j = 0; j < 8; j++)
#pragma unroll
            for (int q = 0; q < 4; q++) acc[i][j][q] = 0.f;

    const int crow = tid >> 1, chalf = tid & 1;
    const unsigned dsto = (unsigned)(crow * 48 + chalf * 16);
    const bool aok = (rowBase + crow) < N_NODES;
    const long long arow = (long long)(rowBase + crow) * 128;

#pragma unroll
    for (int pc = 0; pc < 3; pc++) {
        const __nv_bfloat16 *shi, *slo;
        final_src(pc >> 3, shi, slo);
        unsigned mb = base + (unsigned)pc * 4 * MAT_BYTES;
        int ka = (pc & 7) * 16 + chalf * 8;
        int kw = pc * 16 + chalf * 8;
        cp16(mb + 0 * MAT_BYTES + dsto, shi + arow + ka, aok);
        cp16(mb + 1 * MAT_BYTES + dsto, slo + arow + ka, aok);
        cp16(mb + 2 * MAT_BYTES + dsto, g_fwthi + crow * 512 + kw, true);
        cp16(mb + 3 * MAT_BYTES + dsto, g_fwtlo + crow * 512 + kw, true);
        cp_commit();
    }

    for (int c = 0; c < 32; c++) {
        if (c < 30) cp_wait<2>();
        else if (c == 30) cp_wait<1>();
        else cp_wait<0>();
        __syncthreads();
        mma_chunk(base + (unsigned)(c & 3) * 4 * MAT_BYTES, aoff0, aoff1, woff, acc);
        if (c + 3 < 32) {
            int cn = c + 3;
            const __nv_bfloat16 *shi, *slo;
            final_src(cn >> 3, shi, slo);
            unsigned mb = base + (unsigned)(cn & 3) * 4 * MAT_BYTES;
            int ka = (cn & 7) * 16 + chalf * 8;
            int kw = cn * 16 + chalf * 8;
            cp16(mb + 0 * MAT_BYTES + dsto, shi + arow + ka, aok);
            cp16(mb + 1 * MAT_BYTES + dsto, slo + arow + ka, aok);
            cp16(mb + 2 * MAT_BYTES + dsto, g_fwthi + crow * 512 + kw, true);
            cp16(mb + 3 * MAT_BYTES + dsto, g_fwtlo + crow * 512 + kw, true);
            cp_commit();
        }
    }

#pragma unroll
    for (int ni = 0; ni < 8; ni++) {
        int n0 = wn * 64 + ni * 8 + 2 * (lane & 3);
        float2 bv = *(const float2*)&fb[n0];
#pragma unroll
        for (int mi = 0; mi < 2; mi++) {
            int r0 = rowBase + wm * 32 + mi * 16 + (lane >> 2);
            float* C = acc[mi][ni];
            if (r0 < N_NODES) {
                float2 o = make_float2(C[0] + bv.x, C[1] + bv.y);
                *(float2*)&out[(long long)r0 * 128 + n0] = o;
            }
            if (r0 + 8 < N_NODES) {
                float2 o = make_float2(C[2] + bv.x, C[3] + bv.y);
                *(float2*)&out[(long long)(r0 + 8) * 128 + n0] = o;
            }
        }
    }
}

// ---------------- launch ----------------
extern "C" void kernel_launch(void* const* d_in, const int* in_sizes, int n_in,
                              void* d_out, int out_size) {
    const float* x   = (const float*)d_in[0];
    const int*   ei  = (const int*)d_in[1];
    const float* W1  = (const float*)d_in[2];
    const float* b1  = (const float*)d_in[3];
    const float* W2  = (const float*)d_in[4];
    const float* b2  = (const float*)d_in[5];
    const float* eps = (const float*)d_in[6];
    const float* fw  = (const float*)d_in[7];
    const float* fb  = (const float*)d_in[8];
    float* out = (float*)d_out;

    cudaFuncSetAttribute(mma_gemm_kernel,
                         cudaFuncAttributeMaxDynamicSharedMemorySize, SMEM_BYTES);
    cudaFuncSetAttribute(final_gemm_kernel,
                         cudaFuncAttributeMaxDynamicSharedMemorySize, SMEM_BYTES);

    const int PB = (NELEM / 8 + 255) / 256;          // 3125
    const int EB8 = (N_EDGES / 8 + 255) / 256;       // 313
    const int GB = (N_NODES + 127) / 128;            // 391
    const int AB = (N_NODES * 32 + 255) / 256;       // warp per node

    // fused prep + CSR build
    prep_kernel<<<PB, 256>>>(x, ei, W1, W2, fw);
    hist_kernel<<<EB8, 256>>>(ei);
    bsum_kernel<<<NBLK, 256>>>();
    rowptr_kernel<<<NBLK, 256>>>();
    scatter_kernel<<<EB8, 256>>>(ei);

    // 3 GIN layers
    int hin[3]  = { SEL_X, SEL_H0, SEL_H1 };
    int hout[3] = { SEL_H0, SEL_H1, SEL_H2 };
    for (int l = 0; l < 3; l++) {
        agg_kernel<<<AB, 256>>>(hin[l], eps, l);
        mma_gemm_kernel<<<GB, 256, SMEM_BYTES>>>(SEL_T, 2 * l,     b1 + l * 128, SEL_Z);
        mma_gemm_kernel<<<GB, 256, SMEM_BYTES>>>(SEL_Z, 2 * l + 1, b2 + l * 128, hout[l]);
    }
    final_gemm_kernel<<<GB, 256, SMEM_BYTES>>>(fb, out);
}

// round 16
// speedup vs baseline: 1.2136x; 1.0103x over previous
#include <cuda_runtime.h>
#include <cuda_bf16.h>

#define N_NODES 50000
#define N_EDGES 640000
#define NELEM (N_NODES * 128)
#define NBLK 196

// ---------------- scratch (device globals) ----------------
__device__ __align__(16) __nv_bfloat16 g_xhi[NELEM], g_xlo[NELEM];
__device__ __align__(16) __nv_bfloat16 g_thi[NELEM], g_tlo[NELEM];
__device__ __align__(16) __nv_bfloat16 g_zhi[NELEM], g_zlo[NELEM];
__device__ __align__(16) __nv_bfloat16 g_hhi[3][NELEM], g_hlo[3][NELEM];
__device__ __align__(16) __nv_bfloat16 g_wthi[6][128 * 128], g_wtlo[6][128 * 128];
__device__ __align__(16) __nv_bfloat16 g_fwthi[128 * 512], g_fwtlo[128 * 512];
__device__ int g_rowptr[N_NODES + 1], g_cnt[N_NODES], g_cnt2[N_NODES], g_srcs[N_EDGES];
__device__ int g_is64, g_bsum[256];

#define SEL_X 0
#define SEL_T 1
#define SEL_Z 2
#define SEL_H0 3
#define SEL_H1 4
#define SEL_H2 5

__device__ __forceinline__ void sel_hl(int s, const __nv_bfloat16*& hi,
                                       const __nv_bfloat16*& lo) {
    switch (s) {
        case SEL_X: hi = g_xhi; lo = g_xlo; break;
        case SEL_T: hi = g_thi; lo = g_tlo; break;
        case SEL_Z: hi = g_zhi; lo = g_zlo; break;
        case SEL_H0: hi = g_hhi[0]; lo = g_hlo[0]; break;
        case SEL_H1: hi = g_hhi[1]; lo = g_hlo[1]; break;
        default:     hi = g_hhi[2]; lo = g_hlo[2]; break;
    }
}
__device__ __forceinline__ void sel_out(int s, __nv_bfloat16*& hi, __nv_bfloat16*& lo) {
    switch (s) {
        case SEL_T: hi = g_thi; lo = g_tlo; break;
        case SEL_Z: hi = g_zhi; lo = g_zlo; break;
        case SEL_H0: hi = g_hhi[0]; lo = g_hlo[0]; break;
        case SEL_H1: hi = g_hhi[1]; lo = g_hlo[1]; break;
        default:     hi = g_hhi[2]; lo = g_hlo[2]; break;
    }
}

// ---------------- fused prep: zero cnt + detect dtype + split x + split W ----
__global__ void prep_kernel(const float* __restrict__ x, const int* __restrict__ ei32,
                            const float* __restrict__ W1, const float* __restrict__ W2,
                            const float* __restrict__ fw) {
    int i = blockIdx.x * 256 + threadIdx.x;
    if (i < N_NODES) g_cnt[i] = 0;
    if (i == 0) {
        int ornz = 0;
#pragma unroll
        for (int k = 0; k < 64; k++) ornz |= ei32[2 * k + 1];
        g_is64 = (ornz == 0) ? 1 : 0;
    }
    if (i < 6 * 16384) {
        int m = i >> 14, t = i & 16383;
        int n = t >> 7, k = t & 127;
        int l = m >> 1;
        const float* src = (m & 1) ? W2 : W1;
        float v = src[l * 16384 + k * 128 + n];
        __nv_bfloat16 h = __float2bfloat16_rn(v);
        g_wthi[m][n * 128 + k] = h;
        g_wtlo[m][n * 128 + k] = __float2bfloat16_rn(v - __bfloat162float(h));
    } else if (i < 6 * 16384 + 128 * 512) {
        int t = i - 6 * 16384;
        int n = t >> 9, k = t & 511;
        float v = fw[k * 128 + n];
        __nv_bfloat16 h = __float2bfloat16_rn(v);
        g_fwthi[n * 512 + k] = h;
        g_fwtlo[n * 512 + k] = __float2bfloat16_rn(v - __bfloat162float(h));
    }
    if (i < NELEM / 8) {
        const float4* xp = (const float4*)x;
        float4 v0 = xp[2 * i], v1 = xp[2 * i + 1];
        float v[8] = {v0.x, v0.y, v0.z, v0.w, v1.x, v1.y, v1.z, v1.w};
        uint4 hp, lp;
        __nv_bfloat162* h2 = (__nv_bfloat162*)&hp;
        __nv_bfloat162* l2 = (__nv_bfloat162*)&lp;
#pragma unroll
        for (int j = 0; j < 4; j++) {
            __nv_bfloat16 h0 = __float2bfloat16_rn(v[2 * j]);
            __nv_bfloat16 h1 = __float2bfloat16_rn(v[2 * j + 1]);
            h2[j].x = h0; h2[j].y = h1;
            l2[j].x = __float2bfloat16_rn(v[2 * j] - __bfloat162float(h0));
            l2[j].y = __float2bfloat16_rn(v[2 * j + 1] - __bfloat162float(h1));
        }
        ((uint4*)g_xhi)[i] = hp;
        ((uint4*)g_xlo)[i] = lp;
    }
}

// ---------------- CSR build (8 edges/thread) ----------------
__global__ void hist_kernel(const int* __restrict__ ei32) {
    int e = (blockIdx.x * 256 + threadIdx.x) * 8;
    if (e >= N_EDGES) return;
    int is64 = g_is64;
    int d[8];
    if (is64) {
#pragma unroll
        for (int q = 0; q < 4; q++) {
            int4 a = *(const int4*)&ei32[2 * (N_EDGES + e) + 4 * q];
            d[2 * q] = a.x; d[2 * q + 1] = a.z;
        }
    } else {
        int4 a = *(const int4*)&ei32[N_EDGES + e];
        int4 b = *(const int4*)&ei32[N_EDGES + e + 4];
        d[0] = a.x; d[1] = a.y; d[2] = a.z; d[3] = a.w;
        d[4] = b.x; d[5] = b.y; d[6] = b.z; d[7] = b.w;
    }
#pragma unroll
    for (int q = 0; q < 8; q++)
        if ((unsigned)d[q] < (unsigned)N_NODES) atomicAdd(&g_cnt[d[q]], 1);
}

__global__ void bsum_kernel() {   // per-block sums; also zeroes g_cnt2
    __shared__ int sh[256];
    int t = threadIdx.x, i = blockIdx.x * 256 + t;
    if (i < N_NODES) g_cnt2[i] = 0;
    sh[t] = (i < N_NODES) ? g_cnt[i] : 0;
    __syncthreads();
#pragma unroll
    for (int off = 128; off > 0; off >>= 1) {
        if (t < off) sh[t] += sh[t + off];
        __syncthreads();
    }
    if (t == 0) g_bsum[blockIdx.x] = sh[0];
}

__global__ void rowptr_kernel() {
    __shared__ int sb[256];
    __shared__ int sh[256];
    int t = threadIdx.x, i = blockIdx.x * 256 + t;
    int bv = (t < NBLK) ? g_bsum[t] : 0;
    sb[t] = bv;
    __syncthreads();
#pragma unroll
    for (int off = 1; off < 256; off <<= 1) {
        int a = (t >= off) ? sb[t - off] : 0;
        __syncthreads();
        sb[t] += a;
        __syncthreads();
    }
    int boff = sb[blockIdx.x] - g_bsum[blockIdx.x];
    if (blockIdx.x == 0 && t == 0) g_rowptr[N_NODES] = sb[255];

    int v = (i < N_NODES) ? g_cnt[i] : 0;
    sh[t] = v;
    __syncthreads();
#pragma unroll
    for (int off = 1; off < 256; off <<= 1) {
        int a = (t >= off) ? sh[t - off] : 0;
        __syncthreads();
        sh[t] += a;
        __syncthreads();
    }
    if (i < N_NODES) g_rowptr[i] = boff + sh[t] - v;
}

__global__ void scatter_kernel(const int* __restrict__ ei32) {
    int e = (blockIdx.x * 256 + threadIdx.x) * 8;
    if (e >= N_EDGES) return;
    int is64 = g_is64;
    int s[8], d[8];
    if (is64) {
#pragma unroll
        for (int q = 0; q < 4; q++) {
            int4 a = *(const int4*)&ei32[2 * e + 4 * q];
            s[2 * q] = a.x; s[2 * q + 1] = a.z;
            int4 c = *(const int4*)&ei32[2 * (N_EDGES + e) + 4 * q];
            d[2 * q] = c.x; d[2 * q + 1] = c.z;
        }
    } else {
        int4 a = *(const int4*)&ei32[e];
        int4 b = *(const int4*)&ei32[e + 4];
        s[0] = a.x; s[1] = a.y; s[2] = a.z; s[3] = a.w;
        s[4] = b.x; s[5] = b.y; s[6] = b.z; s[7] = b.w;
        int4 c = *(const int4*)&ei32[N_EDGES + e];
        int4 f = *(const int4*)&ei32[N_EDGES + e + 4];
        d[0] = c.x; d[1] = c.y; d[2] = c.z; d[3] = c.w;
        d[4] = f.x; d[5] = f.y; d[6] = f.z; d[7] = f.w;
    }
#pragma unroll
    for (int q = 0; q < 8; q++) {
        if ((unsigned)d[q] < (unsigned)N_NODES && (unsigned)s[q] < (unsigned)N_NODES) {
            int pos = g_rowptr[d[q]] + atomicAdd(&g_cnt2[d[q]], 1);
            if ((unsigned)pos < (unsigned)N_EDGES) g_srcs[pos] = s[q];
        }
    }
}

// ---------------- aggregation: t = (1+eps)*h + segsum (hi/lo pairs) ---------
__global__ void agg_kernel(int hsel, const float* __restrict__ eps, int l) {
    const __nv_bfloat16 *hib, *lob;
    sel_hl(hsel, hib, lob);
    int wnode = (blockIdx.x * blockDim.x + threadIdx.x) >> 5;
    int lane = threadIdx.x & 31;
    if (wnode >= N_NODES) return;
    int half = lane >> 4;
    int p = lane & 15;
    const uint4* rows = (const uint4*)(half ? lob : hib);
    float acc[8];
#pragma unroll
    for (int j = 0; j < 8; j++) acc[j] = 0.f;

    int beg = g_rowptr[wnode], end = g_rowptr[wnode + 1];
    int i = beg;
    for (; i + 4 <= end; i += 4) {
        int s0 = g_srcs[i], s1 = g_srcs[i + 1];
        int s2 = g_srcs[i + 2], s3 = g_srcs[i + 3];
        uint4 v0 = rows[s0 * 16 + p];
        uint4 v1 = rows[s1 * 16 + p];
        uint4 v2 = rows[s2 * 16 + p];
        uint4 v3 = rows[s3 * 16 + p];
        const __nv_bfloat162* p0 = (const __nv_bfloat162*)&v0;
        const __nv_bfloat162* p1 = (const __nv_bfloat162*)&v1;
        const __nv_bfloat162* p2 = (const __nv_bfloat162*)&v2;
        const __nv_bfloat162* p3 = (const __nv_bfloat162*)&v3;
#pragma unroll
        for (int j = 0; j < 4; j++) {
            float2 f0 = __bfloat1622float2(p0[j]);
            float2 f1 = __bfloat1622float2(p1[j]);
            float2 f2 = __bfloat1622float2(p2[j]);
            float2 f3 = __bfloat1622float2(p3[j]);
            acc[2 * j]     += (f0.x + f1.x) + (f2.x + f3.x);
            acc[2 * j + 1] += (f0.y + f1.y) + (f2.y + f3.y);
        }
    }
    for (; i < end; i++) {
        uint4 v = rows[g_srcs[i] * 16 + p];
        const __nv_bfloat162* pv = (const __nv_bfloat162*)&v;
#pragma unroll
        for (int j = 0; j < 4; j++) {
            float2 f = __bfloat1622float2(pv[j]);
            acc[2 * j] += f.x;
            acc[2 * j + 1] += f.y;
        }
    }
    float e = 1.0f + eps[l];
    {
        uint4 v = rows[wnode * 16 + p];
        const __nv_bfloat162* pv = (const __nv_bfloat162*)&v;
#pragma unroll
        for (int j = 0; j < 4; j++) {
            float2 f = __bfloat1622float2(pv[j]);
            acc[2 * j] += e * f.x;
            acc[2 * j + 1] += e * f.y;
        }
    }
    float tot[8];
#pragma unroll
    for (int j = 0; j < 8; j++)
        tot[j] = acc[j] + __shfl_xor_sync(0xffffffffu, acc[j], 16);
    uint4 outv;
    __nv_bfloat162* o2 = (__nv_bfloat162*)&outv;
#pragma unroll
    for (int j = 0; j < 4; j++) {
        __nv_bfloat16 h0 = __float2bfloat16_rn(tot[2 * j]);
        __nv_bfloat16 h1 = __float2bfloat16_rn(tot[2 * j + 1]);
        if (half == 0) { o2[j].x = h0; o2[j].y = h1; }
        else {
            o2[j].x = __float2bfloat16_rn(tot[2 * j] - __bfloat162float(h0));
            o2[j].y = __float2bfloat16_rn(tot[2 * j + 1] - __bfloat162float(h1));
        }
    }
    uint4* dst = (uint4*)(half ? g_tlo : g_thi);
    dst[wnode * 16 + p] = outv;
}

// ---------------- tensor-core GEMM machinery ----------------
__device__ __forceinline__ void cp16(unsigned s, const void* g, bool pred) {
    int sz = pred ? 16 : 0;
    asm volatile("cp.async.cg.shared.global [%0], [%1], 16, %2;\n"
                 :: "r"(s), "l"(g), "r"(sz));
}
__device__ __forceinline__ void cp_commit() { asm volatile("cp.async.commit_group;\n"); }
template <int N>
__device__ __forceinline__ void cp_wait() {
    asm volatile("cp.async.wait_group %0;\n" :: "n"(N) : "memory");
}

__device__ __forceinline__ void ldsm4(unsigned* r, unsigned addr) {
    asm volatile("ldmatrix.sync.aligned.m8n8.x4.shared.b16 {%0,%1,%2,%3}, [%4];"
                 : "=r"(r[0]), "=r"(r[1]), "=r"(r[2]), "=r"(r[3]) : "r"(addr));
}
__device__ __forceinline__ void mma_bf16(float* c, const unsigned* a, const unsigned* b) {
    asm volatile(
        "mma.sync.aligned.m16n8k16.row.col.f32.bf16.bf16.f32 "
        "{%0,%1,%2,%3},{%4,%5,%6,%7},{%8,%9},{%0,%1,%2,%3};"
        : "+f"(c[0]), "+f"(c[1]), "+f"(c[2]), "+f"(c[3])
        : "r"(a[0]), "r"(a[1]), "r"(a[2]), "r"(a[3]), "r"(b[0]), "r"(b[1]));
}
__device__ __forceinline__ void store_hl(__nv_bfloat16* Ohi, __nv_bfloat16* Olo,
                                         long long off, float v0, float v1) {
    __nv_bfloat16 h0 = __float2bfloat16_rn(v0), h1 = __float2bfloat16_rn(v1);
    __nv_bfloat162 hp; hp.x = h0; hp.y = h1;
    *(__nv_bfloat162*)(Ohi + off) = hp;
    __nv_bfloat162 lp;
    lp.x = __float2bfloat16_rn(v0 - __bfloat162float(h0));
    lp.y = __float2bfloat16_rn(v1 - __bfloat162float(h1));
    *(__nv_bfloat162*)(Olo + off) = lp;
}

// 4-stage dynamic smem: per stage mats {Ahi, Alo, Whi, Wlo}, each 128 rows x 24 bf16
#define MAT_BYTES 6144u
#define NSTAGE 4
#define SMEM_BYTES (NSTAGE * 4 * MAT_BYTES)   // 98304

__device__ __forceinline__ void mma_chunk(unsigned mbase, int aoff0, int aoff1,
                                          const int* woff, float acc[2][8][4]) {
    unsigned ah[2][4], al[2][4];
    ldsm4(ah[0], mbase + 0 * MAT_BYTES + aoff0);
    ldsm4(ah[1], mbase + 0 * MAT_BYTES + aoff1);
    ldsm4(al[0], mbase + 1 * MAT_BYTES + aoff0);
    ldsm4(al[1], mbase + 1 * MAT_BYTES + aoff1);
#pragma unroll
    for (int ng = 0; ng < 4; ng++) {
        unsigned bh[4], bl[4];
        ldsm4(bh, mbase + 2 * MAT_BYTES + woff[ng]);
        ldsm4(bl, mbase + 3 * MAT_BYTES + woff[ng]);
#pragma unroll
        for (int mi = 0; mi < 2; mi++)
#pragma unroll
            for (int ns = 0; ns < 2; ns++) {
                float* C = acc[mi][ng * 2 + ns];
                mma_bf16(C, ah[mi], &bh[ns * 2]);
                mma_bf16(C, ah[mi], &bl[ns * 2]);
                mma_bf16(C, al[mi], &bh[ns * 2]);
            }
    }
}

// ---------------- layer GEMM: out = relu(A @ W + bias), K=128, BM=128 --------
__global__ void __launch_bounds__(256, 2)
mma_gemm_kernel(int a_sel, int w_idx, const float* __restrict__ bias, int o_sel) {
    extern __shared__ __nv_bfloat16 dynsm[];
    const unsigned base = (unsigned)__cvta_generic_to_shared(dynsm);

    const __nv_bfloat16 *Ahi, *Alo;
    sel_hl(a_sel, Ahi, Alo);
    __nv_bfloat16 *Ohi, *Olo;
    sel_out(o_sel, Ohi, Olo);
    const __nv_bfloat16* Whi = g_wthi[w_idx];
    const __nv_bfloat16* Wlo = g_wtlo[w_idx];

    const int tid = threadIdx.x, lane = tid & 31, w = tid >> 5;
    const int wm = w & 3, wn = w >> 2;
    const int rowBase = blockIdx.x * 128;
    const int g = lane >> 3, r = lane & 7;

    const int aoff0 = (wm * 32 + 0 + (g & 1) * 8 + r) * 48 + (g >> 1) * 16;
    const int aoff1 = (wm * 32 + 16 + (g & 1) * 8 + r) * 48 + (g >> 1) * 16;
    int woff[4];
#pragma unroll
    for (int ng = 0; ng < 4; ng++)
        woff[ng] = (wn * 64 + ng * 16 + (g >> 1) * 8 + r) * 48 + (g & 1) * 16;

    float acc[2][8][4];
#pragma unroll
    for (int i = 0; i < 2; i++)
#pragma unroll
        for (int j = 0; j < 8; j++)
#pragma unroll
            for (int q = 0; q < 4; q++) acc[i][j][q] = 0.f;

    const int crow = tid >> 1, chalf = tid & 1;
    const unsigned dsto = (unsigned)(crow * 48 + chalf * 16);
    const bool aok = (rowBase + crow) < N_NODES;
    const long long arow = (long long)(rowBase + crow) * 128;

#pragma unroll
    for (int pc = 0; pc < 3; pc++) {
        unsigned mb = base + (unsigned)pc * 4 * MAT_BYTES;
        int kb = pc * 16 + chalf * 8;
        cp16(mb + 0 * MAT_BYTES + dsto, Ahi + arow + kb, aok);
        cp16(mb + 1 * MAT_BYTES + dsto, Alo + arow + kb, aok);
        cp16(mb + 2 * MAT_BYTES + dsto, Whi + crow * 128 + kb, true);
        cp16(mb + 3 * MAT_BYTES + dsto, Wlo + crow * 128 + kb, true);
        cp_commit();
    }

#pragma unroll
    for (int c = 0; c < 8; c++) {
        if (c < 6) cp_wait<2>();
        else if (c == 6) cp_wait<1>();
        else cp_wait<0>();
        __syncthreads();
        mma_chunk(base + (unsigned)(c & 3) * 4 * MAT_BYTES, aoff0, aoff1, woff, acc);
        if (c + 3 < 8) {
            unsigned mb = base + (unsigned)((c + 3) & 3) * 4 * MAT_BYTES;
            int kb = (c + 3) * 16 + chalf * 8;
            cp16(mb + 0 * MAT_BYTES + dsto, Ahi + arow + kb, aok);
            cp16(mb + 1 * MAT_BYTES + dsto, Alo + arow + kb, aok);
            cp16(mb + 2 * MAT_BYTES + dsto, Whi + crow * 128 + kb, true);
            cp16(mb + 3 * MAT_BYTES + dsto, Wlo + crow * 128 + kb, true);
            cp_commit();
        }
    }

#pragma unroll
    for (int ni = 0; ni < 8; ni++) {
        int n0 = wn * 64 + ni * 8 + 2 * (lane & 3);
        float2 bv = *(const float2*)&bias[n0];
#pragma unroll
        for (int mi = 0; mi < 2; mi++) {
            int r0 = rowBase + wm * 32 + mi * 16 + (lane >> 2);
            float* C = acc[mi][ni];
            float v0 = fmaxf(C[0] + bv.x, 0.f), v1 = fmaxf(C[1] + bv.y, 0.f);
            float v2 = fmaxf(C[2] + bv.x, 0.f), v3 = fmaxf(C[3] + bv.y, 0.f);
            if (r0 < N_NODES) store_hl(Ohi, Olo, (long long)r0 * 128 + n0, v0, v1);
            if (r0 + 8 < N_NODES) store_hl(Ohi, Olo, (long long)(r0 + 8) * 128 + n0, v2, v3);
        }
    }
}

// ---------------- final GEMM: out = concat(x,h0,h1,h2) @ fw + fb, K=512 ------
__device__ __forceinline__ void final_src(int s, const __nv_bfloat16*& hi,
                                          const __nv_bfloat16*& lo) {
    switch (s) {
        case 0: hi = g_xhi; lo = g_xlo; break;
        case 1: hi = g_hhi[0]; lo = g_hlo[0]; break;
        case 2: hi = g_hhi[1]; lo = g_hlo[1]; break;
        default: hi = g_hhi[2]; lo = g_hlo[2]; break;
    }
}

__global__ void __launch_bounds__(256, 2)
final_gemm_kernel(const float* __restrict__ fb, float* __restrict__ out) {
    extern __shared__ __nv_bfloat16 dynsm[];
    const unsigned base = (unsigned)__cvta_generic_to_shared(dynsm);

    const int tid = threadIdx.x, lane = tid & 31, w = tid >> 5;
    const int wm = w & 3, wn = w >> 2;
    const int rowBase = blockIdx.x * 128;
    const int g = lane >> 3, r = lane & 7;

    const int aoff0 = (wm * 32 + 0 + (g & 1) * 8 + r) * 48 + (g >> 1) * 16;
    const int aoff1 = (wm * 32 + 16 + (g & 1) * 8 + r) * 48 + (g >> 1) * 16;
    int woff[4];
#pragma unroll
    for (int ng = 0; ng < 4; ng++)
        woff[ng] = (wn * 64 + ng * 16 + (g >> 1) * 8 + r) * 48 + (g & 1) * 16;

    float acc[2][8][4];
#pragma unroll
    for (int i = 0; i < 2; i++)
#pragma unroll
        for (int j = 0; j < 8; j++)
#pragma unroll
            for (int q = 0; q < 4; q++) acc[i][j][q] = 0.f;

    const int crow = tid >> 1, chalf = tid & 1;
    const unsigned dsto = (unsigned)(crow * 48 + chalf * 16);
    const bool aok = (rowBase + crow) < N_NODES;
    const long long arow = (long long)(rowBase + crow) * 128;

#pragma unroll
    for (int pc = 0; pc < 3; pc++) {
        const __nv_bfloat16 *shi, *slo;
        final_src(pc >> 3, shi, slo);
        unsigned mb = base + (unsigned)pc * 4 * MAT_BYTES;
        int ka = (pc & 7) * 16 + chalf * 8;
        int kw = pc * 16 + chalf * 8;
        cp16(mb + 0 * MAT_BYTES + dsto, shi + arow + ka, aok);
        cp16(mb + 1 * MAT_BYTES + dsto, slo + arow + ka, aok);
        cp16(mb + 2 * MAT_BYTES + dsto, g_fwthi + crow * 512 + kw, true);
        cp16(mb + 3 * MAT_BYTES + dsto, g_fwtlo + crow * 512 + kw, true);
        cp_commit();
    }

    for (int c = 0; c < 32; c++) {
        if (c < 30) cp_wait<2>();
        else if (c == 30) cp_wait<1>();
        else cp_wait<0>();
        __syncthreads();
        mma_chunk(base + (unsigned)(c & 3) * 4 * MAT_BYTES, aoff0, aoff1, woff, acc);
        if (c + 3 < 32) {
            int cn = c + 3;
            const __nv_bfloat16 *shi, *slo;
            final_src(cn >> 3, shi, slo);
            unsigned mb = base + (unsigned)(cn & 3) * 4 * MAT_BYTES;
            int ka = (cn & 7) * 16 + chalf * 8;
            int kw = cn * 16 + chalf * 8;
            cp16(mb + 0 * MAT_BYTES + dsto, shi + arow + ka, aok);
            cp16(mb + 1 * MAT_BYTES + dsto, slo + arow + ka, aok);
            cp16(mb + 2 * MAT_BYTES + dsto, g_fwthi + crow * 512 + kw, true);
            cp16(mb + 3 * MAT_BYTES + dsto, g_fwtlo + crow * 512 + kw, true);
            cp_commit();
        }
    }

#pragma unroll
    for (int ni = 0; ni < 8; ni++) {
        int n0 = wn * 64 + ni * 8 + 2 * (lane & 3);
        float2 bv = *(const float2*)&fb[n0];
#pragma unroll
        for (int mi = 0; mi < 2; mi++) {
            int r0 = rowBase + wm * 32 + mi * 16 + (lane >> 2);
            float* C = acc[mi][ni];
            if (r0 < N_NODES) {
                float2 o = make_float2(C[0] + bv.x, C[1] + bv.y);
                *(float2*)&out[(long long)r0 * 128 + n0] = o;
            }
            if (r0 + 8 < N_NODES) {
                float2 o = make_float2(C[2] + bv.x, C[3] + bv.y);
                *(float2*)&out[(long long)(r0 + 8) * 128 + n0] = o;
            }
        }
    }
}

// ---------------- launch ----------------
extern "C" void kernel_launch(void* const* d_in, const int* in_sizes, int n_in,
                              void* d_out, int out_size) {
    const float* x   = (const float*)d_in[0];
    const int*   ei  = (const int*)d_in[1];
    const float* W1  = (const float*)d_in[2];
    const float* b1  = (const float*)d_in[3];
    const float* W2  = (const float*)d_in[4];
    const float* b2  = (const float*)d_in[5];
    const float* eps = (const float*)d_in[6];
    const float* fw  = (const float*)d_in[7];
    const float* fb  = (const float*)d_in[8];
    float* out = (float*)d_out;

    cudaFuncSetAttribute(mma_gemm_kernel,
                         cudaFuncAttributeMaxDynamicSharedMemorySize, SMEM_BYTES);
    cudaFuncSetAttribute(final_gemm_kernel,
                         cudaFuncAttributeMaxDynamicSharedMemorySize, SMEM_BYTES);

    const int PB = (NELEM / 8 + 255) / 256;          // 3125
    const int EB8 = (N_EDGES / 8 + 255) / 256;       // 313
    const int GB = (N_NODES + 127) / 128;            // 391
    const int AB = (N_NODES * 32 + 255) / 256;       // warp per node

    // fused prep + CSR build
    prep_kernel<<<PB, 256>>>(x, ei, W1, W2, fw);
    hist_kernel<<<EB8, 256>>>(ei);
    bsum_kernel<<<NBLK, 256>>>();
    rowptr_kernel<<<NBLK, 256>>>();
    scatter_kernel<<<EB8, 256>>>(ei);

    // 3 GIN layers
    int hin[3]  = { SEL_X, SEL_H0, SEL_H1 };
    int hout[3] = { SEL_H0, SEL_H1, SEL_H2 };
    for (int l = 0; l < 3; l++) {
        agg_kernel<<<AB, 256>>>(hin[l], eps, l);
        mma_gemm_kernel<<<GB, 256, SMEM_BYTES>>>(SEL_T, 2 * l,     b1 + l * 128, SEL_Z);
        mma_gemm_kernel<<<GB, 256, SMEM_BYTES>>>(SEL_Z, 2 * l + 1, b2 + l * 128, hout[l]);
    }
    final_gemm_kernel<<<GB, 256, SMEM_BYTES>>>(fb, out);
}